// round 1
// baseline (speedup 1.0000x reference)
#include <cuda_runtime.h>
#include <math.h>

#define N_NODES 20000
#define HID 256
#define HEADS 8
#define DH 32
#define DEG 32
#define TOPK 16

// Scratch (no cudaMalloc allowed)
__device__ float g_q[N_NODES * HID];
__device__ float g_k[N_NODES * HID];
__device__ float g_v[N_NODES * HID];
__device__ float g_agg[N_NODES * HID];

// ---------------------------------------------------------------------------
// GEMM: C[i,o] = sum_k A[i,k] * W[o,k] + bias[o], optional leaky-relu.
// A: [M,K] row-major, W: [Nout,K] row-major (i.e., C = A @ W^T + b).
// 128x128 tile, BK=16, 256 threads, 8x8 microtile.
// ---------------------------------------------------------------------------
#define BM 128
#define BN 128
#define BK 16
#define TM 8
#define TN 8

__global__ __launch_bounds__(256, 2)
void gemm_nt_kernel(const float* __restrict__ A, const float* __restrict__ W,
                    const float* __restrict__ bias, float* __restrict__ C,
                    int M, int Nout, int K, int leaky) {
    __shared__ float As[BK][BM];
    __shared__ float Bs[BK][BN];

    const int tid = threadIdx.x;
    const int tr = tid / 16;       // 0..15
    const int tc = tid % 16;       // 0..15
    const int row0 = blockIdx.y * BM;
    const int col0 = blockIdx.x * BN;

    // loader mapping: thread -> (row within tile, k-offset 0/8)
    const int lrow = tid >> 1;           // 0..127
    const int lk   = (tid & 1) * 8;      // 0 or 8

    const int ar = row0 + lrow;          // A global row
    const int wr = col0 + lrow;          // W global row (output index)

    float acc[TM][TN];
#pragma unroll
    for (int i = 0; i < TM; i++)
#pragma unroll
        for (int j = 0; j < TN; j++) acc[i][j] = 0.0f;

    for (int k0 = 0; k0 < K; k0 += BK) {
        // load from global
        float4 a0 = make_float4(0.f, 0.f, 0.f, 0.f), a1 = a0;
        float4 b0 = a0, b1 = a0;
        if (ar < M) {
            const float* ap = A + (size_t)ar * K + k0 + lk;
            a0 = *(const float4*)(ap);
            a1 = *(const float4*)(ap + 4);
        }
        if (wr < Nout) {
            const float* wp = W + (size_t)wr * K + k0 + lk;
            b0 = *(const float4*)(wp);
            b1 = *(const float4*)(wp + 4);
        }
        __syncthreads();  // previous compute done before overwriting smem
        As[lk + 0][lrow] = a0.x; As[lk + 1][lrow] = a0.y;
        As[lk + 2][lrow] = a0.z; As[lk + 3][lrow] = a0.w;
        As[lk + 4][lrow] = a1.x; As[lk + 5][lrow] = a1.y;
        As[lk + 6][lrow] = a1.z; As[lk + 7][lrow] = a1.w;
        Bs[lk + 0][lrow] = b0.x; Bs[lk + 1][lrow] = b0.y;
        Bs[lk + 2][lrow] = b0.z; Bs[lk + 3][lrow] = b0.w;
        Bs[lk + 4][lrow] = b1.x; Bs[lk + 5][lrow] = b1.y;
        Bs[lk + 6][lrow] = b1.z; Bs[lk + 7][lrow] = b1.w;
        __syncthreads();

#pragma unroll
        for (int kk = 0; kk < BK; kk++) {
            float a[TM], b[TN];
            float4 av0 = *(const float4*)&As[kk][tr * TM];
            float4 av1 = *(const float4*)&As[kk][tr * TM + 4];
            float4 bv0 = *(const float4*)&Bs[kk][tc * TN];
            float4 bv1 = *(const float4*)&Bs[kk][tc * TN + 4];
            a[0]=av0.x; a[1]=av0.y; a[2]=av0.z; a[3]=av0.w;
            a[4]=av1.x; a[5]=av1.y; a[6]=av1.z; a[7]=av1.w;
            b[0]=bv0.x; b[1]=bv0.y; b[2]=bv0.z; b[3]=bv0.w;
            b[4]=bv1.x; b[5]=bv1.y; b[6]=bv1.z; b[7]=bv1.w;
#pragma unroll
            for (int i = 0; i < TM; i++)
#pragma unroll
                for (int j = 0; j < TN; j++)
                    acc[i][j] = fmaf(a[i], b[j], acc[i][j]);
        }
    }

    // epilogue
    const int crow = row0 + tr * TM;
    const int ccol = col0 + tc * TN;
#pragma unroll
    for (int i = 0; i < TM; i++) {
        if (crow + i < M) {
#pragma unroll
            for (int j = 0; j < TN; j++) {
                float v = acc[i][j] + bias[ccol + j];
                if (leaky) v = (v > 0.0f) ? v : 0.01f * v;
                C[(size_t)(crow + i) * Nout + ccol + j] = v;
            }
        }
    }
}

// ---------------------------------------------------------------------------
// Attention: block per node (256 threads = 8 warps), warp per head.
// Phase A (warp 0): top-16 rank of edge weights + normalization.
// Phase B (lane = neighbor): score = <k_nbr_head, q_head>, warp softmax.
// Phase C (lane = dim): coalesced v aggregation.
// ---------------------------------------------------------------------------
__global__ __launch_bounds__(256)
void attn_kernel(const int* __restrict__ nbr, const float* __restrict__ ew,
                 float* __restrict__ agg) {
    const int i = blockIdx.x;
    const int tid = threadIdx.x;
    const int warp = tid >> 5;
    const int lane = tid & 31;

    __shared__ float s_q[HID];
    __shared__ float s_w[DEG];
    __shared__ int   s_nbr[DEG];

    s_q[tid] = g_q[(size_t)i * HID + tid];

    if (warp == 0) {
        float w = ew[(size_t)i * DEG + lane];
        s_nbr[lane] = nbr[(size_t)i * DEG + lane];
        // rank via all-pairs comparison (matches stable double-argsort)
        int rank = 0;
#pragma unroll
        for (int l = 0; l < DEG; l++) {
            float wl = __shfl_sync(0xffffffffu, w, l);
            rank += (wl > w) || (wl == w && l < lane);
        }
        float wm = (rank < TOPK) ? w : 0.0f;
        float s = wm;
#pragma unroll
        for (int off = 16; off; off >>= 1)
            s += __shfl_xor_sync(0xffffffffu, s, off);
        s_w[lane] = wm / (s + 1e-5f);
    }
    __syncthreads();

    const int hd = warp;
    const float* qh = s_q + hd * DH;

    // score for neighbor = lane
    const int nb = s_nbr[lane];
    const float* krow = g_k + (size_t)nb * HID + hd * DH;
    float score = 0.0f;
#pragma unroll
    for (int d4 = 0; d4 < DH / 4; d4++) {
        float4 kv = *(const float4*)(krow + d4 * 4);
        score = fmaf(kv.x, qh[d4 * 4 + 0], score);
        score = fmaf(kv.y, qh[d4 * 4 + 1], score);
        score = fmaf(kv.z, qh[d4 * 4 + 2], score);
        score = fmaf(kv.w, qh[d4 * 4 + 3], score);
    }
    const float inv_sqrt_dh = 0.17677669529663687f;  // 1/sqrt(32)
    float logit = score * s_w[lane] * inv_sqrt_dh;

    // warp softmax over the 32 neighbors
    float m = logit;
#pragma unroll
    for (int off = 16; off; off >>= 1)
        m = fmaxf(m, __shfl_xor_sync(0xffffffffu, m, off));
    float e = __expf(logit - m);
    float se = e;
#pragma unroll
    for (int off = 16; off; off >>= 1)
        se += __shfl_xor_sync(0xffffffffu, se, off);
    float attn = e / se;

    // aggregation: lane = output dim, coalesced 128B loads per neighbor
    float acc = 0.0f;
#pragma unroll
    for (int j = 0; j < DEG; j++) {
        float a = __shfl_sync(0xffffffffu, attn, j);
        int nbj = s_nbr[j];
        acc = fmaf(a, g_v[(size_t)nbj * HID + hd * DH + lane], acc);
    }
    agg[(size_t)i * HID + hd * DH + lane] = acc;
}

// ---------------------------------------------------------------------------
// Launch
// ---------------------------------------------------------------------------
extern "C" void kernel_launch(void* const* d_in, const int* in_sizes, int n_in,
                              void* d_out, int out_size) {
    const float* h   = (const float*)d_in[0];
    const int*   nbr = (const int*)d_in[1];
    const float* ew  = (const float*)d_in[2];
    const float* W_q = (const float*)d_in[3];
    const float* b_q = (const float*)d_in[4];
    const float* W_k = (const float*)d_in[5];
    const float* b_k = (const float*)d_in[6];
    const float* W_v = (const float*)d_in[7];
    const float* b_v = (const float*)d_in[8];
    const float* W_o = (const float*)d_in[9];
    const float* b_o = (const float*)d_in[10];
    float* out = (float*)d_out;

    float *q, *k, *v, *agg;
    cudaGetSymbolAddress((void**)&q, g_q);
    cudaGetSymbolAddress((void**)&k, g_k);
    cudaGetSymbolAddress((void**)&v, g_v);
    cudaGetSymbolAddress((void**)&agg, g_agg);

    dim3 grid_proj(HID / BN, (N_NODES + BM - 1) / BM);
    gemm_nt_kernel<<<grid_proj, 256>>>(h, W_q, b_q, q, N_NODES, HID, HID, 0);
    gemm_nt_kernel<<<grid_proj, 256>>>(h, W_k, b_k, k, N_NODES, HID, HID, 0);
    gemm_nt_kernel<<<grid_proj, 256>>>(h, W_v, b_v, v, N_NODES, HID, HID, 0);

    attn_kernel<<<N_NODES, 256>>>(nbr, ew, agg);

    gemm_nt_kernel<<<grid_proj, 256>>>(agg, W_o, b_o, out, N_NODES, HID, HID, 1);
}

// round 4
// speedup vs baseline: 1.7785x; 1.7785x over previous
#include <cuda_runtime.h>
#include <cuda_bf16.h>
#include <cstdint>

#define N_NODES 20000
#define HID 256
#define HEADS 8
#define DH 32
#define DEG 32
#define TOPK 16

#define MPAD 20032          // 20000 padded to multiple of 64

// ---------------------------------------------------------------------------
// Scratch (__device__ globals; no cudaMalloc). Zero-initialized; pad rows of
// the bf16 buffers are never written -> stay zero.
// ---------------------------------------------------------------------------
__device__ float g_q[N_NODES * HID];
__device__ float g_k[N_NODES * HID];
__device__ float g_v[N_NODES * HID];
__device__ float g_agg[N_NODES * HID];
__device__ __align__(16) __nv_bfloat16 g_ah_hi[MPAD * HID];
__device__ __align__(16) __nv_bfloat16 g_ah_lo[MPAD * HID];
__device__ __align__(16) __nv_bfloat16 g_ag_hi[MPAD * HID];
__device__ __align__(16) __nv_bfloat16 g_ag_lo[MPAD * HID];
__device__ __align__(16) __nv_bfloat16 g_w_hi[4][HID * HID];
__device__ __align__(16) __nv_bfloat16 g_w_lo[4][HID * HID];

// ---------------------------------------------------------------------------
// Split: fp32 -> (hi, lo) bf16 pair, plain row-major.
// ---------------------------------------------------------------------------
__device__ __forceinline__ void split8(const float* vals, uint32_t* hw, uint32_t* lw) {
#pragma unroll
    for (int p = 0; p < 4; p++) {
        __nv_bfloat16 h0 = __float2bfloat16(vals[2 * p]);
        __nv_bfloat16 h1 = __float2bfloat16(vals[2 * p + 1]);
        __nv_bfloat16 l0 = __float2bfloat16(vals[2 * p]     - __bfloat162float(h0));
        __nv_bfloat16 l1 = __float2bfloat16(vals[2 * p + 1] - __bfloat162float(h1));
        hw[p] = (uint32_t)__bfloat16_as_ushort(h0) | ((uint32_t)__bfloat16_as_ushort(h1) << 16);
        lw[p] = (uint32_t)__bfloat16_as_ushort(l0) | ((uint32_t)__bfloat16_as_ushort(l1) << 16);
    }
}

__global__ void split_kernel(const float* __restrict__ src,
                             __nv_bfloat16* __restrict__ hi,
                             __nv_bfloat16* __restrict__ lo, int n8) {
    int g = blockIdx.x * blockDim.x + threadIdx.x;
    if (g >= n8) return;
    const float4* s = (const float4*)(src) + g * 2;
    float4 v0 = s[0], v1 = s[1];
    float vals[8] = {v0.x, v0.y, v0.z, v0.w, v1.x, v1.y, v1.z, v1.w};
    uint32_t hw[4], lw[4];
    split8(vals, hw, lw);
    *(uint4*)(hi + (size_t)g * 8) = make_uint4(hw[0], hw[1], hw[2], hw[3]);
    *(uint4*)(lo + (size_t)g * 8) = make_uint4(lw[0], lw[1], lw[2], lw[3]);
}

// ---------------------------------------------------------------------------
// bf16 mma.sync GEMM: C[m,n] = sum_k A[m,k]*W[n,k] + bias[n] (+leaky)
// CTA: 64x64 tile, BK=32, 128 threads = 4 warps (warp tile 32x32).
// 3 products: Ah*Wh + Ah*Wl + Al*Wh.
// ---------------------------------------------------------------------------
#define BM 64
#define BN 64
#define BK 32
#define SA 40   // smem row stride in bf16 (80B) -> conflict-free frag loads

__device__ __forceinline__ void mma16816(float* c, uint32_t a0, uint32_t a1,
                                         uint32_t a2, uint32_t a3,
                                         uint32_t b0, uint32_t b1) {
    asm volatile(
        "mma.sync.aligned.m16n8k16.row.col.f32.bf16.bf16.f32 "
        "{%0,%1,%2,%3}, {%4,%5,%6,%7}, {%8,%9}, {%0,%1,%2,%3};"
        : "+f"(c[0]), "+f"(c[1]), "+f"(c[2]), "+f"(c[3])
        : "r"(a0), "r"(a1), "r"(a2), "r"(a3), "r"(b0), "r"(b1));
}

// store 16 bf16 (2 x uint4 worth) into an 8B-aligned smem row segment
__device__ __forceinline__ void st16(__nv_bfloat16* dst, uint4 v0, uint4 v1) {
    *(uint2*)(dst + 0)  = make_uint2(v0.x, v0.y);
    *(uint2*)(dst + 4)  = make_uint2(v0.z, v0.w);
    *(uint2*)(dst + 8)  = make_uint2(v1.x, v1.y);
    *(uint2*)(dst + 12) = make_uint2(v1.z, v1.w);
}

__global__ void __launch_bounds__(128)
gemm_mma(const __nv_bfloat16* __restrict__ Ahi, const __nv_bfloat16* __restrict__ Alo,
         const __nv_bfloat16* __restrict__ Whi, const __nv_bfloat16* __restrict__ Wlo,
         const float* __restrict__ bias, float* __restrict__ C, int leaky) {
    __shared__ __nv_bfloat16 sAh[BM][SA], sAl[BM][SA], sBh[BN][SA], sBl[BN][SA];

    const int tid = threadIdx.x;
    const int warp = tid >> 5, lane = tid & 31;
    const int g = lane >> 2, t = lane & 3;           // mma fragment coords
    const int m0 = blockIdx.y * BM;
    const int n0 = blockIdx.x * BN;
    const int wm = (warp >> 1) * 32, wn = (warp & 1) * 32;

    // loader mapping: tid -> (row 0..63, 16-elem segment 0/16)
    const int lrow = tid >> 1;
    const int lseg = (tid & 1) * 16;

    float acc[2][4][4];
#pragma unroll
    for (int mt = 0; mt < 2; mt++)
#pragma unroll
        for (int nt = 0; nt < 4; nt++)
#pragma unroll
            for (int r = 0; r < 4; r++) acc[mt][nt][r] = 0.0f;

    for (int k0 = 0; k0 < HID; k0 += BK) {
        const __nv_bfloat16* pA = Ahi + (size_t)(m0 + lrow) * HID + k0 + lseg;
        const __nv_bfloat16* pAl = Alo + (size_t)(m0 + lrow) * HID + k0 + lseg;
        const __nv_bfloat16* pB = Whi + (size_t)(n0 + lrow) * HID + k0 + lseg;
        const __nv_bfloat16* pBl = Wlo + (size_t)(n0 + lrow) * HID + k0 + lseg;
        uint4 vAh0 = *(const uint4*)(pA);      uint4 vAh1 = *(const uint4*)(pA + 8);
        uint4 vAl0 = *(const uint4*)(pAl);     uint4 vAl1 = *(const uint4*)(pAl + 8);
        uint4 vBh0 = *(const uint4*)(pB);      uint4 vBh1 = *(const uint4*)(pB + 8);
        uint4 vBl0 = *(const uint4*)(pBl);     uint4 vBl1 = *(const uint4*)(pBl + 8);
        __syncthreads();  // previous iteration's fragment reads done
        st16(&sAh[lrow][lseg], vAh0, vAh1);
        st16(&sAl[lrow][lseg], vAl0, vAl1);
        st16(&sBh[lrow][lseg], vBh0, vBh1);
        st16(&sBl[lrow][lseg], vBl0, vBl1);
        __syncthreads();

#pragma unroll
        for (int ks = 0; ks < BK; ks += 16) {
            uint32_t ah[2][4], al[2][4], bh[4][2], bl[4][2];
#pragma unroll
            for (int mt = 0; mt < 2; mt++) {
                int r = wm + mt * 16;
                ah[mt][0] = *(const uint32_t*)&sAh[r + g][ks + 2 * t];
                ah[mt][1] = *(const uint32_t*)&sAh[r + g + 8][ks + 2 * t];
                ah[mt][2] = *(const uint32_t*)&sAh[r + g][ks + 2 * t + 8];
                ah[mt][3] = *(const uint32_t*)&sAh[r + g + 8][ks + 2 * t + 8];
                al[mt][0] = *(const uint32_t*)&sAl[r + g][ks + 2 * t];
                al[mt][1] = *(const uint32_t*)&sAl[r + g + 8][ks + 2 * t];
                al[mt][2] = *(const uint32_t*)&sAl[r + g][ks + 2 * t + 8];
                al[mt][3] = *(const uint32_t*)&sAl[r + g + 8][ks + 2 * t + 8];
            }
#pragma unroll
            for (int nt = 0; nt < 4; nt++) {
                int n = wn + nt * 8 + g;
                bh[nt][0] = *(const uint32_t*)&sBh[n][ks + 2 * t];
                bh[nt][1] = *(const uint32_t*)&sBh[n][ks + 2 * t + 8];
                bl[nt][0] = *(const uint32_t*)&sBl[n][ks + 2 * t];
                bl[nt][1] = *(const uint32_t*)&sBl[n][ks + 2 * t + 8];
            }
#pragma unroll
            for (int mt = 0; mt < 2; mt++)
#pragma unroll
                for (int nt = 0; nt < 4; nt++) {
                    mma16816(acc[mt][nt], ah[mt][0], ah[mt][1], ah[mt][2], ah[mt][3],
                             bh[nt][0], bh[nt][1]);
                    mma16816(acc[mt][nt], ah[mt][0], ah[mt][1], ah[mt][2], ah[mt][3],
                             bl[nt][0], bl[nt][1]);
                    mma16816(acc[mt][nt], al[mt][0], al[mt][1], al[mt][2], al[mt][3],
                             bh[nt][0], bh[nt][1]);
                }
        }
    }

    // epilogue: frag thread holds rows (g, g+8), cols (2t, 2t+1)
#pragma unroll
    for (int mt = 0; mt < 2; mt++) {
#pragma unroll
        for (int nt = 0; nt < 4; nt++) {
            int col = n0 + wn + nt * 8 + 2 * t;
            float b0 = bias[col], b1 = bias[col + 1];
#pragma unroll
            for (int h = 0; h < 2; h++) {
                int row = m0 + wm + mt * 16 + g + h * 8;
                if (row < N_NODES) {
                    float v0 = acc[mt][nt][2 * h + 0] + b0;
                    float v1 = acc[mt][nt][2 * h + 1] + b1;
                    if (leaky) {
                        v0 = (v0 > 0.0f) ? v0 : 0.01f * v0;
                        v1 = (v1 > 0.0f) ? v1 : 0.01f * v1;
                    }
                    *(float2*)&C[(size_t)row * HID + col] = make_float2(v0, v1);
                }
            }
        }
    }
}

// ---------------------------------------------------------------------------
// Attention: block per node, warp per head; k rows staged in smem (coalesced).
// ---------------------------------------------------------------------------
__global__ __launch_bounds__(256)
void attn_kernel(const int* __restrict__ nbr, const float* __restrict__ ew,
                 float* __restrict__ agg) {
    const int i = blockIdx.x;
    const int tid = threadIdx.x;
    const int warp = tid >> 5;
    const int lane = tid & 31;

    __shared__ float s_k[DEG][260];   // pad 260 -> conflict-free LDS.128
    __shared__ float s_q[HID];
    __shared__ float s_w[DEG];
    __shared__ int   s_nbr[DEG];

    s_q[tid] = g_q[(size_t)i * HID + tid];

    if (warp == 0) {
        float w = ew[(size_t)i * DEG + lane];
        s_nbr[lane] = nbr[(size_t)i * DEG + lane];
        int rank = 0;
#pragma unroll
        for (int l = 0; l < DEG; l++) {
            float wl = __shfl_sync(0xffffffffu, w, l);
            rank += (wl > w) || (wl == w && l < lane);
        }
        float wm = (rank < TOPK) ? w : 0.0f;
        float s = wm;
#pragma unroll
        for (int off = 16; off; off >>= 1)
            s += __shfl_xor_sync(0xffffffffu, s, off);
        s_w[lane] = wm / (s + 1e-5f);
    }

    // stage neighbor k rows (warp w loads rows w*4 .. w*4+3, coalesced float4)
#pragma unroll
    for (int jj = 0; jj < 4; jj++) {
        int j = warp * 4 + jj;
        int nb = __ldg(&nbr[(size_t)i * DEG + j]);
        const float4* src = (const float4*)(g_k + (size_t)nb * HID);
#pragma unroll
        for (int it = 0; it < 2; it++) {
            int f = it * 32 + lane;
            *(float4*)&s_k[j][f * 4] = src[f];
        }
    }
    __syncthreads();

    const int hd = warp;
    const float* qh = s_q + hd * DH;
    const float* krow = &s_k[lane][hd * DH];
    float score = 0.0f;
#pragma unroll
    for (int d4 = 0; d4 < DH / 4; d4++) {
        float4 kv = *(const float4*)(krow + d4 * 4);
        score = fmaf(kv.x, qh[d4 * 4 + 0], score);
        score = fmaf(kv.y, qh[d4 * 4 + 1], score);
        score = fmaf(kv.z, qh[d4 * 4 + 2], score);
        score = fmaf(kv.w, qh[d4 * 4 + 3], score);
    }
    float logit = score * s_w[lane] * 0.17677669529663687f;  // 1/sqrt(32)

    float m = logit;
#pragma unroll
    for (int off = 16; off; off >>= 1)
        m = fmaxf(m, __shfl_xor_sync(0xffffffffu, m, off));
    float e = __expf(logit - m);
    float se = e;
#pragma unroll
    for (int off = 16; off; off >>= 1)
        se += __shfl_xor_sync(0xffffffffu, se, off);
    float attn = e / se;

    float acc = 0.0f;
#pragma unroll
    for (int j = 0; j < DEG; j++) {
        float a = __shfl_sync(0xffffffffu, attn, j);
        acc = fmaf(a, g_v[(size_t)s_nbr[j] * HID + hd * DH + lane], acc);
    }
    agg[(size_t)i * HID + hd * DH + lane] = acc;
}

// ---------------------------------------------------------------------------
// Launch
// ---------------------------------------------------------------------------
extern "C" void kernel_launch(void* const* d_in, const int* in_sizes, int n_in,
                              void* d_out, int out_size) {
    const float* h   = (const float*)d_in[0];
    const int*   nbr = (const int*)d_in[1];
    const float* ew  = (const float*)d_in[2];
    const float* W_q = (const float*)d_in[3];
    const float* b_q = (const float*)d_in[4];
    const float* W_k = (const float*)d_in[5];
    const float* b_k = (const float*)d_in[6];
    const float* W_v = (const float*)d_in[7];
    const float* b_v = (const float*)d_in[8];
    const float* W_o = (const float*)d_in[9];
    const float* b_o = (const float*)d_in[10];
    float* out = (float*)d_out;

    float *q, *k, *v, *agg;
    __nv_bfloat16 *ah_hi, *ah_lo, *ag_hi, *ag_lo, *w_hi, *w_lo;
    cudaGetSymbolAddress((void**)&q, g_q);
    cudaGetSymbolAddress((void**)&k, g_k);
    cudaGetSymbolAddress((void**)&v, g_v);
    cudaGetSymbolAddress((void**)&agg, g_agg);
    cudaGetSymbolAddress((void**)&ah_hi, g_ah_hi);
    cudaGetSymbolAddress((void**)&ah_lo, g_ah_lo);
    cudaGetSymbolAddress((void**)&ag_hi, g_ag_hi);
    cudaGetSymbolAddress((void**)&ag_lo, g_ag_lo);
    cudaGetSymbolAddress((void**)&w_hi, g_w_hi);
    cudaGetSymbolAddress((void**)&w_lo, g_w_lo);

    const int nA8 = N_NODES * HID / 8;
    const int nW8 = HID * HID / 8;

    split_kernel<<<(nA8 + 255) / 256, 256>>>(h, ah_hi, ah_lo, nA8);
    const float* Ws[4] = {W_q, W_k, W_v, W_o};
    for (int wi = 0; wi < 4; wi++)
        split_kernel<<<(nW8 + 255) / 256, 256>>>(Ws[wi],
            w_hi + (size_t)wi * HID * HID, w_lo + (size_t)wi * HID * HID, nW8);

    dim3 grid(HID / BN, MPAD / BM);
    gemm_mma<<<grid, 128>>>(ah_hi, ah_lo, w_hi + 0 * (size_t)HID * HID,
                            w_lo + 0 * (size_t)HID * HID, b_q, q, 0);
    gemm_mma<<<grid, 128>>>(ah_hi, ah_lo, w_hi + 1 * (size_t)HID * HID,
                            w_lo + 1 * (size_t)HID * HID, b_k, k, 0);
    gemm_mma<<<grid, 128>>>(ah_hi, ah_lo, w_hi + 2 * (size_t)HID * HID,
                            w_lo + 2 * (size_t)HID * HID, b_v, v, 0);

    attn_kernel<<<N_NODES, 256>>>(nbr, ew, agg);

    split_kernel<<<(nA8 + 255) / 256, 256>>>(agg, ag_hi, ag_lo, nA8);
    gemm_mma<<<grid, 128>>>(ag_hi, ag_lo, w_hi + 3 * (size_t)HID * HID,
                            w_lo + 3 * (size_t)HID * HID, b_o, out, 1);
}

// round 5
// speedup vs baseline: 2.0880x; 1.1740x over previous
#include <cuda_runtime.h>
#include <cuda_bf16.h>
#include <cstdint>

#define N_NODES 20000
#define HID 256
#define HEADS 8
#define DH 32
#define DEG 32
#define TOPK 16

#define MPAD 20032          // 20000 padded to multiple of 64
#define KPAD 264            // attn smem k row stride (bf16)

// ---------------------------------------------------------------------------
// Scratch (__device__ globals). Zero-initialized; pad rows never written.
// ---------------------------------------------------------------------------
__device__ float g_q[N_NODES * HID];
__device__ float g_v[N_NODES * HID];
__device__ __align__(16) __nv_bfloat16 g_kb[N_NODES * HID];       // k in bf16
__device__ __align__(16) __nv_bfloat16 g_ah_hi[MPAD * HID];
__device__ __align__(16) __nv_bfloat16 g_ah_lo[MPAD * HID];
__device__ __align__(16) __nv_bfloat16 g_ag_hi[MPAD * HID];
__device__ __align__(16) __nv_bfloat16 g_ag_lo[MPAD * HID];
__device__ __align__(16) __nv_bfloat16 g_w_hi[4][HID * HID];
__device__ __align__(16) __nv_bfloat16 g_w_lo[4][HID * HID];

// ---------------------------------------------------------------------------
// Splits: fp32 -> (hi, lo) bf16
// ---------------------------------------------------------------------------
__device__ __forceinline__ void split8(const float* vals, uint32_t* hw, uint32_t* lw) {
#pragma unroll
    for (int p = 0; p < 4; p++) {
        __nv_bfloat16 h0 = __float2bfloat16(vals[2 * p]);
        __nv_bfloat16 h1 = __float2bfloat16(vals[2 * p + 1]);
        __nv_bfloat16 l0 = __float2bfloat16(vals[2 * p]     - __bfloat162float(h0));
        __nv_bfloat16 l1 = __float2bfloat16(vals[2 * p + 1] - __bfloat162float(h1));
        hw[p] = (uint32_t)__bfloat16_as_ushort(h0) | ((uint32_t)__bfloat16_as_ushort(h1) << 16);
        lw[p] = (uint32_t)__bfloat16_as_ushort(l0) | ((uint32_t)__bfloat16_as_ushort(l1) << 16);
    }
}

__global__ void split_kernel(const float* __restrict__ src,
                             __nv_bfloat16* __restrict__ hi,
                             __nv_bfloat16* __restrict__ lo, int n8) {
    int g = blockIdx.x * blockDim.x + threadIdx.x;
    if (g >= n8) return;
    const float4* s = (const float4*)(src) + g * 2;
    float4 v0 = s[0], v1 = s[1];
    float vals[8] = {v0.x, v0.y, v0.z, v0.w, v1.x, v1.y, v1.z, v1.w};
    uint32_t hw[4], lw[4];
    split8(vals, hw, lw);
    *(uint4*)(hi + (size_t)g * 8) = make_uint4(hw[0], hw[1], hw[2], hw[3]);
    *(uint4*)(lo + (size_t)g * 8) = make_uint4(lw[0], lw[1], lw[2], lw[3]);
}

// all 4 weight matrices in one launch: g in [0, 4*8192)
__global__ void split_w_kernel(const float* __restrict__ w0, const float* __restrict__ w1,
                               const float* __restrict__ w2, const float* __restrict__ w3,
                               __nv_bfloat16* __restrict__ hi, __nv_bfloat16* __restrict__ lo) {
    int g = blockIdx.x * blockDim.x + threadIdx.x;
    if (g >= 4 * (HID * HID / 8)) return;
    int wi = g >> 13, idx = g & 8191;
    const float* src = (wi == 0) ? w0 : (wi == 1) ? w1 : (wi == 2) ? w2 : w3;
    const float4* s = (const float4*)(src) + idx * 2;
    float4 v0 = s[0], v1 = s[1];
    float vals[8] = {v0.x, v0.y, v0.z, v0.w, v1.x, v1.y, v1.z, v1.w};
    uint32_t hw[4], lw[4];
    split8(vals, hw, lw);
    size_t off = (size_t)wi * HID * HID + (size_t)idx * 8;
    *(uint4*)(hi + off) = make_uint4(hw[0], hw[1], hw[2], hw[3]);
    *(uint4*)(lo + off) = make_uint4(lw[0], lw[1], lw[2], lw[3]);
}

// ---------------------------------------------------------------------------
// bf16 mma.sync GEMM mainloop (software-pipelined). CTA 64x64, BK=32,
// 128 threads = 4 warps. 3 products: Ah*Wh + Ah*Wl + Al*Wh.
// ---------------------------------------------------------------------------
#define BM 64
#define BN 64
#define BK 32
#define SA 40

__device__ __forceinline__ void mma16816(float* c, uint32_t a0, uint32_t a1,
                                         uint32_t a2, uint32_t a3,
                                         uint32_t b0, uint32_t b1) {
    asm volatile(
        "mma.sync.aligned.m16n8k16.row.col.f32.bf16.bf16.f32 "
        "{%0,%1,%2,%3}, {%4,%5,%6,%7}, {%8,%9}, {%0,%1,%2,%3};"
        : "+f"(c[0]), "+f"(c[1]), "+f"(c[2]), "+f"(c[3])
        : "r"(a0), "r"(a1), "r"(a2), "r"(a3), "r"(b0), "r"(b1));
}

__device__ __forceinline__ void st16(__nv_bfloat16* dst, uint4 v0, uint4 v1) {
    *(uint2*)(dst + 0)  = make_uint2(v0.x, v0.y);
    *(uint2*)(dst + 4)  = make_uint2(v0.z, v0.w);
    *(uint2*)(dst + 8)  = make_uint2(v1.x, v1.y);
    *(uint2*)(dst + 12) = make_uint2(v1.z, v1.w);
}

struct SmemTiles {
    __nv_bfloat16 Ah[BM][SA], Al[BM][SA], Bh[BN][SA], Bl[BN][SA];
};

__device__ __forceinline__ void mma_mainloop(
    const __nv_bfloat16* __restrict__ Ahi, const __nv_bfloat16* __restrict__ Alo,
    const __nv_bfloat16* __restrict__ Whi, const __nv_bfloat16* __restrict__ Wlo,
    int m0, int n0, SmemTiles& sm, float (&acc)[2][4][4]) {
    const int tid = threadIdx.x;
    const int warp = tid >> 5, lane = tid & 31;
    const int g = lane >> 2, t = lane & 3;
    const int wm = (warp >> 1) * 32, wn = (warp & 1) * 32;
    const int lrow = tid >> 1;
    const int lseg = (tid & 1) * 16;

    const __nv_bfloat16* pA  = Ahi + (size_t)(m0 + lrow) * HID + lseg;
    const __nv_bfloat16* pAl = Alo + (size_t)(m0 + lrow) * HID + lseg;
    const __nv_bfloat16* pB  = Whi + (size_t)(n0 + lrow) * HID + lseg;
    const __nv_bfloat16* pBl = Wlo + (size_t)(n0 + lrow) * HID + lseg;

#pragma unroll
    for (int mt = 0; mt < 2; mt++)
#pragma unroll
        for (int nt = 0; nt < 4; nt++)
#pragma unroll
            for (int r = 0; r < 4; r++) acc[mt][nt][r] = 0.0f;

    // prologue: prefetch tile 0
    uint4 vAh0 = *(const uint4*)(pA);      uint4 vAh1 = *(const uint4*)(pA + 8);
    uint4 vAl0 = *(const uint4*)(pAl);     uint4 vAl1 = *(const uint4*)(pAl + 8);
    uint4 vBh0 = *(const uint4*)(pB);      uint4 vBh1 = *(const uint4*)(pB + 8);
    uint4 vBl0 = *(const uint4*)(pBl);     uint4 vBl1 = *(const uint4*)(pBl + 8);

    for (int k0 = 0; k0 < HID; k0 += BK) {
        __syncthreads();  // previous iteration's fragment reads done
        st16(&sm.Ah[lrow][lseg], vAh0, vAh1);
        st16(&sm.Al[lrow][lseg], vAl0, vAl1);
        st16(&sm.Bh[lrow][lseg], vBh0, vBh1);
        st16(&sm.Bl[lrow][lseg], vBl0, vBl1);
        __syncthreads();

        // prefetch next tile: LDG latency overlaps the MMA block below
        if (k0 + BK < HID) {
            int o = k0 + BK;
            vAh0 = *(const uint4*)(pA + o);      vAh1 = *(const uint4*)(pA + o + 8);
            vAl0 = *(const uint4*)(pAl + o);     vAl1 = *(const uint4*)(pAl + o + 8);
            vBh0 = *(const uint4*)(pB + o);      vBh1 = *(const uint4*)(pB + o + 8);
            vBl0 = *(const uint4*)(pBl + o);     vBl1 = *(const uint4*)(pBl + o + 8);
        }

#pragma unroll
        for (int ks = 0; ks < BK; ks += 16) {
            uint32_t ah[2][4], al[2][4], bh[4][2], bl[4][2];
#pragma unroll
            for (int mt = 0; mt < 2; mt++) {
                int r = wm + mt * 16;
                ah[mt][0] = *(const uint32_t*)&sm.Ah[r + g][ks + 2 * t];
                ah[mt][1] = *(const uint32_t*)&sm.Ah[r + g + 8][ks + 2 * t];
                ah[mt][2] = *(const uint32_t*)&sm.Ah[r + g][ks + 2 * t + 8];
                ah[mt][3] = *(const uint32_t*)&sm.Ah[r + g + 8][ks + 2 * t + 8];
                al[mt][0] = *(const uint32_t*)&sm.Al[r + g][ks + 2 * t];
                al[mt][1] = *(const uint32_t*)&sm.Al[r + g + 8][ks + 2 * t];
                al[mt][2] = *(const uint32_t*)&sm.Al[r + g][ks + 2 * t + 8];
                al[mt][3] = *(const uint32_t*)&sm.Al[r + g + 8][ks + 2 * t + 8];
            }
#pragma unroll
            for (int nt = 0; nt < 4; nt++) {
                int n = wn + nt * 8 + g;
                bh[nt][0] = *(const uint32_t*)&sm.Bh[n][ks + 2 * t];
                bh[nt][1] = *(const uint32_t*)&sm.Bh[n][ks + 2 * t + 8];
                bl[nt][0] = *(const uint32_t*)&sm.Bl[n][ks + 2 * t];
                bl[nt][1] = *(const uint32_t*)&sm.Bl[n][ks + 2 * t + 8];
            }
#pragma unroll
            for (int mt = 0; mt < 2; mt++)
#pragma unroll
                for (int nt = 0; nt < 4; nt++) {
                    mma16816(acc[mt][nt], ah[mt][0], ah[mt][1], ah[mt][2], ah[mt][3],
                             bh[nt][0], bh[nt][1]);
                    mma16816(acc[mt][nt], ah[mt][0], ah[mt][1], ah[mt][2], ah[mt][3],
                             bl[nt][0], bl[nt][1]);
                    mma16816(acc[mt][nt], al[mt][0], al[mt][1], al[mt][2], al[mt][3],
                             bh[nt][0], bh[nt][1]);
                }
        }
    }
}

// Fused q/k/v projection: grid.x = 12; which = x/4 selects weight+output.
// q, v -> fp32; k -> bf16.
__global__ void __launch_bounds__(128)
gemm_qkv(const __nv_bfloat16* __restrict__ Ahi, const __nv_bfloat16* __restrict__ Alo,
         const __nv_bfloat16* __restrict__ whi, const __nv_bfloat16* __restrict__ wlo,
         const float* __restrict__ bq, const float* __restrict__ bk,
         const float* __restrict__ bv,
         float* __restrict__ qo, __nv_bfloat16* __restrict__ ko, float* __restrict__ vo) {
    __shared__ SmemTiles sm;
    const int which = blockIdx.x >> 2;
    const int n0 = (blockIdx.x & 3) * BN;
    const int m0 = blockIdx.y * BM;
    const float* bias = (which == 0) ? bq : (which == 1) ? bk : bv;

    float acc[2][4][4];
    mma_mainloop(Ahi, Alo, whi + (size_t)which * HID * HID,
                 wlo + (size_t)which * HID * HID, m0, n0, sm, acc);

    const int warp = threadIdx.x >> 5, lane = threadIdx.x & 31;
    const int g = lane >> 2, t = lane & 3;
    const int wm = (warp >> 1) * 32, wn = (warp & 1) * 32;
#pragma unroll
    for (int mt = 0; mt < 2; mt++)
#pragma unroll
        for (int nt = 0; nt < 4; nt++) {
            int col = n0 + wn + nt * 8 + 2 * t;
            float b0 = bias[col], b1 = bias[col + 1];
#pragma unroll
            for (int hh = 0; hh < 2; hh++) {
                int row = m0 + wm + mt * 16 + g + hh * 8;
                if (row < N_NODES) {
                    float v0 = acc[mt][nt][2 * hh + 0] + b0;
                    float v1 = acc[mt][nt][2 * hh + 1] + b1;
                    if (which == 1) {
                        uint32_t pk = (uint32_t)__bfloat16_as_ushort(__float2bfloat16(v0)) |
                                      ((uint32_t)__bfloat16_as_ushort(__float2bfloat16(v1)) << 16);
                        *(uint32_t*)&ko[(size_t)row * HID + col] = pk;
                    } else {
                        float* dst = (which == 0) ? qo : vo;
                        *(float2*)&dst[(size_t)row * HID + col] = make_float2(v0, v1);
                    }
                }
            }
        }
}

// Output projection: reads agg hi/lo, fp32 out + leaky relu.
__global__ void __launch_bounds__(128)
gemm_o(const __nv_bfloat16* __restrict__ Ahi, const __nv_bfloat16* __restrict__ Alo,
       const __nv_bfloat16* __restrict__ Whi, const __nv_bfloat16* __restrict__ Wlo,
       const float* __restrict__ bias, float* __restrict__ C) {
    __shared__ SmemTiles sm;
    const int n0 = blockIdx.x * BN;
    const int m0 = blockIdx.y * BM;

    float acc[2][4][4];
    mma_mainloop(Ahi, Alo, Whi, Wlo, m0, n0, sm, acc);

    const int warp = threadIdx.x >> 5, lane = threadIdx.x & 31;
    const int g = lane >> 2, t = lane & 3;
    const int wm = (warp >> 1) * 32, wn = (warp & 1) * 32;
#pragma unroll
    for (int mt = 0; mt < 2; mt++)
#pragma unroll
        for (int nt = 0; nt < 4; nt++) {
            int col = n0 + wn + nt * 8 + 2 * t;
            float b0 = bias[col], b1 = bias[col + 1];
#pragma unroll
            for (int hh = 0; hh < 2; hh++) {
                int row = m0 + wm + mt * 16 + g + hh * 8;
                if (row < N_NODES) {
                    float v0 = acc[mt][nt][2 * hh + 0] + b0;
                    float v1 = acc[mt][nt][2 * hh + 1] + b1;
                    v0 = (v0 > 0.0f) ? v0 : 0.01f * v0;
                    v1 = (v1 > 0.0f) ? v1 : 0.01f * v1;
                    *(float2*)&C[(size_t)row * HID + col] = make_float2(v0, v1);
                }
            }
        }
}

// ---------------------------------------------------------------------------
// Attention: block per node, warp per head; k staged in smem as bf16.
// Epilogue writes agg directly as split hi/lo bf16.
// ---------------------------------------------------------------------------
__global__ __launch_bounds__(256)
void attn_kernel(const int* __restrict__ nbr, const float* __restrict__ ew,
                 __nv_bfloat16* __restrict__ agg_hi, __nv_bfloat16* __restrict__ agg_lo) {
    const int i = blockIdx.x;
    const int tid = threadIdx.x;
    const int warp = tid >> 5;
    const int lane = tid & 31;

    __shared__ __nv_bfloat16 s_k[DEG][KPAD];
    __shared__ float s_q[HID];
    __shared__ float s_w[DEG];
    __shared__ int   s_nbr[DEG];

    s_q[tid] = g_q[(size_t)i * HID + tid];

    if (warp == 0) {
        float w = ew[(size_t)i * DEG + lane];
        s_nbr[lane] = nbr[(size_t)i * DEG + lane];
        int rank = 0;
#pragma unroll
        for (int l = 0; l < DEG; l++) {
            float wl = __shfl_sync(0xffffffffu, w, l);
            rank += (wl > w) || (wl == w && l < lane);
        }
        float wm = (rank < TOPK) ? w : 0.0f;
        float s = wm;
#pragma unroll
        for (int off = 16; off; off >>= 1)
            s += __shfl_xor_sync(0xffffffffu, s, off);
        s_w[lane] = wm / (s + 1e-5f);
    }

    // stage neighbor k rows (bf16): warp w stages rows w*4..w*4+3;
    // one row = 32 lanes x uint4 (8 bf16) = 256 bf16, fully coalesced.
#pragma unroll
    for (int jj = 0; jj < 4; jj++) {
        int j = warp * 4 + jj;
        int nb = __ldg(&nbr[(size_t)i * DEG + j]);
        uint4 vkb = *(const uint4*)(g_kb + (size_t)nb * HID + lane * 8);
        *(uint4*)&s_k[j][lane * 8] = vkb;
    }
    __syncthreads();

    // score: warp = head, lane = neighbor
    const int hd = warp;
    const float* qh = s_q + hd * DH;
    const __nv_bfloat16* krow = &s_k[lane][hd * DH];
    float score = 0.0f;
#pragma unroll
    for (int d2 = 0; d2 < DH / 2; d2++) {
        float2 kv = __bfloat1622float2(*(const __nv_bfloat162*)(krow + d2 * 2));
        score = fmaf(kv.x, qh[d2 * 2 + 0], score);
        score = fmaf(kv.y, qh[d2 * 2 + 1], score);
    }
    float logit = score * s_w[lane] * 0.17677669529663687f;  // 1/sqrt(32)

    float m = logit;
#pragma unroll
    for (int off = 16; off; off >>= 1)
        m = fmaxf(m, __shfl_xor_sync(0xffffffffu, m, off));
    float e = __expf(logit - m);
    float se = e;
#pragma unroll
    for (int off = 16; off; off >>= 1)
        se += __shfl_xor_sync(0xffffffffu, se, off);
    float attn = e / se;

    // aggregation: lane = dim, coalesced 128B per neighbor (v fp32)
    float acc = 0.0f;
#pragma unroll
    for (int j = 0; j < DEG; j++) {
        float a = __shfl_sync(0xffffffffu, attn, j);
        acc = fmaf(a, g_v[(size_t)s_nbr[j] * HID + hd * DH + lane], acc);
    }

    // fused split epilogue
    __nv_bfloat16 hi = __float2bfloat16(acc);
    __nv_bfloat16 lo = __float2bfloat16(acc - __bfloat162float(hi));
    size_t o = (size_t)i * HID + hd * DH + lane;
    agg_hi[o] = hi;
    agg_lo[o] = lo;
}

// ---------------------------------------------------------------------------
// Launch
// ---------------------------------------------------------------------------
extern "C" void kernel_launch(void* const* d_in, const int* in_sizes, int n_in,
                              void* d_out, int out_size) {
    const float* h   = (const float*)d_in[0];
    const int*   nbr = (const int*)d_in[1];
    const float* ew  = (const float*)d_in[2];
    const float* W_q = (const float*)d_in[3];
    const float* b_q = (const float*)d_in[4];
    const float* W_k = (const float*)d_in[5];
    const float* b_k = (const float*)d_in[6];
    const float* W_v = (const float*)d_in[7];
    const float* b_v = (const float*)d_in[8];
    const float* W_o = (const float*)d_in[9];
    const float* b_o = (const float*)d_in[10];
    float* out = (float*)d_out;

    float *q, *v;
    __nv_bfloat16 *kb, *ah_hi, *ah_lo, *ag_hi, *ag_lo, *w_hi, *w_lo;
    cudaGetSymbolAddress((void**)&q, g_q);
    cudaGetSymbolAddress((void**)&v, g_v);
    cudaGetSymbolAddress((void**)&kb, g_kb);
    cudaGetSymbolAddress((void**)&ah_hi, g_ah_hi);
    cudaGetSymbolAddress((void**)&ah_lo, g_ah_lo);
    cudaGetSymbolAddress((void**)&ag_hi, g_ag_hi);
    cudaGetSymbolAddress((void**)&ag_lo, g_ag_lo);
    cudaGetSymbolAddress((void**)&w_hi, g_w_hi);
    cudaGetSymbolAddress((void**)&w_lo, g_w_lo);

    const int nA8 = N_NODES * HID / 8;

    split_kernel<<<(nA8 + 255) / 256, 256>>>(h, ah_hi, ah_lo, nA8);
    split_w_kernel<<<(4 * HID * HID / 8 + 255) / 256, 256>>>(W_q, W_k, W_v, W_o, w_hi, w_lo);

    dim3 grid_qkv(12, MPAD / BM);
    gemm_qkv<<<grid_qkv, 128>>>(ah_hi, ah_lo, w_hi, w_lo, b_q, b_k, b_v, q, kb, v);

    attn_kernel<<<N_NODES, 256>>>(nbr, ew, ag_hi, ag_lo);

    dim3 grid_o(4, MPAD / BM);
    gemm_o<<<grid_o, 128>>>(ag_hi, ag_lo, w_hi + 3 * (size_t)HID * HID,
                            w_lo + 3 * (size_t)HID * HID, b_o, out);
}

// round 6
// speedup vs baseline: 2.3002x; 1.1017x over previous
#include <cuda_runtime.h>
#include <cuda_bf16.h>
#include <cstdint>

#define N_NODES 20000
#define HID 256
#define HEADS 8
#define DH 32
#define DEG 32
#define TOPK 16

#define MPAD 20032          // 20000 padded to multiple of 64
#define KPAD 264            // attn smem k row stride (bf16)

// ---------------------------------------------------------------------------
// Scratch (__device__ globals). Zero-initialized; pad rows never written.
// ---------------------------------------------------------------------------
__device__ float g_q[N_NODES * HID];
__device__ float g_v[N_NODES * HID];
__device__ __align__(16) __nv_bfloat16 g_kb[N_NODES * HID];       // k in bf16
__device__ __align__(16) __nv_bfloat16 g_ah_hi[MPAD * HID];
__device__ __align__(16) __nv_bfloat16 g_ah_lo[MPAD * HID];
__device__ __align__(16) __nv_bfloat16 g_ag_hi[MPAD * HID];
__device__ __align__(16) __nv_bfloat16 g_ag_lo[MPAD * HID];
__device__ __align__(16) __nv_bfloat16 g_w_hi[4][HID * HID];
__device__ __align__(16) __nv_bfloat16 g_w_lo[4][HID * HID];

// ---------------------------------------------------------------------------
// Splits: fp32 -> (hi, lo) bf16
// ---------------------------------------------------------------------------
__device__ __forceinline__ void split8(const float* vals, uint32_t* hw, uint32_t* lw) {
#pragma unroll
    for (int p = 0; p < 4; p++) {
        __nv_bfloat16 h0 = __float2bfloat16(vals[2 * p]);
        __nv_bfloat16 h1 = __float2bfloat16(vals[2 * p + 1]);
        __nv_bfloat16 l0 = __float2bfloat16(vals[2 * p]     - __bfloat162float(h0));
        __nv_bfloat16 l1 = __float2bfloat16(vals[2 * p + 1] - __bfloat162float(h1));
        hw[p] = (uint32_t)__bfloat16_as_ushort(h0) | ((uint32_t)__bfloat16_as_ushort(h1) << 16);
        lw[p] = (uint32_t)__bfloat16_as_ushort(l0) | ((uint32_t)__bfloat16_as_ushort(l1) << 16);
    }
}

__global__ void split_kernel(const float* __restrict__ src,
                             __nv_bfloat16* __restrict__ hi,
                             __nv_bfloat16* __restrict__ lo, int n8) {
    int g = blockIdx.x * blockDim.x + threadIdx.x;
    if (g >= n8) return;
    const float4* s = (const float4*)(src) + g * 2;
    float4 v0 = s[0], v1 = s[1];
    float vals[8] = {v0.x, v0.y, v0.z, v0.w, v1.x, v1.y, v1.z, v1.w};
    uint32_t hw[4], lw[4];
    split8(vals, hw, lw);
    *(uint4*)(hi + (size_t)g * 8) = make_uint4(hw[0], hw[1], hw[2], hw[3]);
    *(uint4*)(lo + (size_t)g * 8) = make_uint4(lw[0], lw[1], lw[2], lw[3]);
}

__global__ void split_w_kernel(const float* __restrict__ w0, const float* __restrict__ w1,
                               const float* __restrict__ w2, const float* __restrict__ w3,
                               __nv_bfloat16* __restrict__ hi, __nv_bfloat16* __restrict__ lo) {
    int g = blockIdx.x * blockDim.x + threadIdx.x;
    if (g >= 4 * (HID * HID / 8)) return;
    int wi = g >> 13, idx = g & 8191;
    const float* src = (wi == 0) ? w0 : (wi == 1) ? w1 : (wi == 2) ? w2 : w3;
    const float4* s = (const float4*)(src) + idx * 2;
    float4 v0 = s[0], v1 = s[1];
    float vals[8] = {v0.x, v0.y, v0.z, v0.w, v1.x, v1.y, v1.z, v1.w};
    uint32_t hw[4], lw[4];
    split8(vals, hw, lw);
    size_t off = (size_t)wi * HID * HID + (size_t)idx * 8;
    *(uint4*)(hi + off) = make_uint4(hw[0], hw[1], hw[2], hw[3]);
    *(uint4*)(lo + off) = make_uint4(lw[0], lw[1], lw[2], lw[3]);
}

// ---------------------------------------------------------------------------
// bf16 mma.sync GEMM with 3-stage cp.async pipeline. CTA 64x64, BK=32,
// 128 threads = 4 warps. 3 products: Ah*Wh + Ah*Wl + Al*Wh.
// ---------------------------------------------------------------------------
#define BM 64
#define BN 64
#define BK 32
#define SA 40
#define STAGES 3
#define NITER (HID / BK)   // 8

struct Stage {
    __nv_bfloat16 Ah[BM][SA], Al[BM][SA], Bh[BN][SA], Bl[BN][SA];
};
#define SMEM_GEMM (STAGES * (int)sizeof(Stage))

__device__ __forceinline__ void mma16816(float* c, uint32_t a0, uint32_t a1,
                                         uint32_t a2, uint32_t a3,
                                         uint32_t b0, uint32_t b1) {
    asm volatile(
        "mma.sync.aligned.m16n8k16.row.col.f32.bf16.bf16.f32 "
        "{%0,%1,%2,%3}, {%4,%5,%6,%7}, {%8,%9}, {%0,%1,%2,%3};"
        : "+f"(c[0]), "+f"(c[1]), "+f"(c[2]), "+f"(c[3])
        : "r"(a0), "r"(a1), "r"(a2), "r"(a3), "r"(b0), "r"(b1));
}

__device__ __forceinline__ void cpa16(uint32_t dst, const void* src) {
    asm volatile("cp.async.cg.shared.global [%0], [%1], 16;" :: "r"(dst), "l"(src));
}
__device__ __forceinline__ void cpa_commit() {
    asm volatile("cp.async.commit_group;" ::: "memory");
}
__device__ __forceinline__ void cpa_wait2() {
    asm volatile("cp.async.wait_group 2;" ::: "memory");
}

__device__ __forceinline__ void prefetch_stage(
    Stage* st, const __nv_bfloat16* pA, const __nv_bfloat16* pAl,
    const __nv_bfloat16* pB, const __nv_bfloat16* pBl,
    int k0, int lrow, int lseg) {
    uint32_t a;
    a = (uint32_t)__cvta_generic_to_shared(&st->Ah[lrow][lseg]);
    cpa16(a, pA + k0);  cpa16(a + 16, pA + k0 + 8);
    a = (uint32_t)__cvta_generic_to_shared(&st->Al[lrow][lseg]);
    cpa16(a, pAl + k0); cpa16(a + 16, pAl + k0 + 8);
    a = (uint32_t)__cvta_generic_to_shared(&st->Bh[lrow][lseg]);
    cpa16(a, pB + k0);  cpa16(a + 16, pB + k0 + 8);
    a = (uint32_t)__cvta_generic_to_shared(&st->Bl[lrow][lseg]);
    cpa16(a, pBl + k0); cpa16(a + 16, pBl + k0 + 8);
}

__device__ __forceinline__ void mma_mainloop(
    const __nv_bfloat16* __restrict__ Ahi, const __nv_bfloat16* __restrict__ Alo,
    const __nv_bfloat16* __restrict__ Whi, const __nv_bfloat16* __restrict__ Wlo,
    int m0, int n0, Stage* stages, float (&acc)[2][4][4]) {
    const int tid = threadIdx.x;
    const int warp = tid >> 5, lane = tid & 31;
    const int g = lane >> 2, t = lane & 3;
    const int wm = (warp >> 1) * 32, wn = (warp & 1) * 32;
    const int lrow = tid >> 1;
    const int lseg = (tid & 1) * 16;

    const __nv_bfloat16* pA  = Ahi + (size_t)(m0 + lrow) * HID + lseg;
    const __nv_bfloat16* pAl = Alo + (size_t)(m0 + lrow) * HID + lseg;
    const __nv_bfloat16* pB  = Whi + (size_t)(n0 + lrow) * HID + lseg;
    const __nv_bfloat16* pBl = Wlo + (size_t)(n0 + lrow) * HID + lseg;

#pragma unroll
    for (int mt = 0; mt < 2; mt++)
#pragma unroll
        for (int nt = 0; nt < 4; nt++)
#pragma unroll
            for (int r = 0; r < 4; r++) acc[mt][nt][r] = 0.0f;

    // prologue: fill the ring
#pragma unroll
    for (int s = 0; s < STAGES; s++) {
        prefetch_stage(&stages[s], pA, pAl, pB, pBl, s * BK, lrow, lseg);
        cpa_commit();
    }

    for (int i = 0; i < NITER; i++) {
        cpa_wait2();           // oldest group (stage i%3) landed
        __syncthreads();
        Stage& st = stages[i % STAGES];

#pragma unroll
        for (int ks = 0; ks < BK; ks += 16) {
            uint32_t ah[2][4], al[2][4], bh[4][2], bl[4][2];
#pragma unroll
            for (int mt = 0; mt < 2; mt++) {
                int r = wm + mt * 16;
                ah[mt][0] = *(const uint32_t*)&st.Ah[r + g][ks + 2 * t];
                ah[mt][1] = *(const uint32_t*)&st.Ah[r + g + 8][ks + 2 * t];
                ah[mt][2] = *(const uint32_t*)&st.Ah[r + g][ks + 2 * t + 8];
                ah[mt][3] = *(const uint32_t*)&st.Ah[r + g + 8][ks + 2 * t + 8];
                al[mt][0] = *(const uint32_t*)&st.Al[r + g][ks + 2 * t];
                al[mt][1] = *(const uint32_t*)&st.Al[r + g + 8][ks + 2 * t];
                al[mt][2] = *(const uint32_t*)&st.Al[r + g][ks + 2 * t + 8];
                al[mt][3] = *(const uint32_t*)&st.Al[r + g + 8][ks + 2 * t + 8];
            }
#pragma unroll
            for (int nt = 0; nt < 4; nt++) {
                int n = wn + nt * 8 + g;
                bh[nt][0] = *(const uint32_t*)&st.Bh[n][ks + 2 * t];
                bh[nt][1] = *(const uint32_t*)&st.Bh[n][ks + 2 * t + 8];
                bl[nt][0] = *(const uint32_t*)&st.Bl[n][ks + 2 * t];
                bl[nt][1] = *(const uint32_t*)&st.Bl[n][ks + 2 * t + 8];
            }
#pragma unroll
            for (int mt = 0; mt < 2; mt++)
#pragma unroll
                for (int nt = 0; nt < 4; nt++) {
                    mma16816(acc[mt][nt], ah[mt][0], ah[mt][1], ah[mt][2], ah[mt][3],
                             bh[nt][0], bh[nt][1]);
                    mma16816(acc[mt][nt], ah[mt][0], ah[mt][1], ah[mt][2], ah[mt][3],
                             bl[nt][0], bl[nt][1]);
                    mma16816(acc[mt][nt], al[mt][0], al[mt][1], al[mt][2], al[mt][3],
                             bh[nt][0], bh[nt][1]);
                }
        }

        __syncthreads();       // all warps done reading stage i%3
        if (i + STAGES < NITER)
            prefetch_stage(&stages[i % STAGES], pA, pAl, pB, pBl,
                           (i + STAGES) * BK, lrow, lseg);
        cpa_commit();          // commit (possibly empty) to keep counts uniform
    }
}

// Fused q/k/v projection: grid.x = 12; which = x/4 selects weight+output.
__global__ void __launch_bounds__(128)
gemm_qkv(const __nv_bfloat16* __restrict__ Ahi, const __nv_bfloat16* __restrict__ Alo,
         const __nv_bfloat16* __restrict__ whi, const __nv_bfloat16* __restrict__ wlo,
         const float* __restrict__ bq, const float* __restrict__ bk,
         const float* __restrict__ bv,
         float* __restrict__ qo, __nv_bfloat16* __restrict__ ko, float* __restrict__ vo) {
    extern __shared__ Stage stages[];
    const int which = blockIdx.x >> 2;
    const int n0 = (blockIdx.x & 3) * BN;
    const int m0 = blockIdx.y * BM;
    const float* bias = (which == 0) ? bq : (which == 1) ? bk : bv;

    float acc[2][4][4];
    mma_mainloop(Ahi, Alo, whi + (size_t)which * HID * HID,
                 wlo + (size_t)which * HID * HID, m0, n0, stages, acc);

    const int warp = threadIdx.x >> 5, lane = threadIdx.x & 31;
    const int g = lane >> 2, t = lane & 3;
    const int wm = (warp >> 1) * 32, wn = (warp & 1) * 32;
#pragma unroll
    for (int mt = 0; mt < 2; mt++)
#pragma unroll
        for (int nt = 0; nt < 4; nt++) {
            int col = n0 + wn + nt * 8 + 2 * t;
            float b0 = bias[col], b1 = bias[col + 1];
#pragma unroll
            for (int hh = 0; hh < 2; hh++) {
                int row = m0 + wm + mt * 16 + g + hh * 8;
                if (row < N_NODES) {
                    float v0 = acc[mt][nt][2 * hh + 0] + b0;
                    float v1 = acc[mt][nt][2 * hh + 1] + b1;
                    if (which == 1) {
                        uint32_t pk = (uint32_t)__bfloat16_as_ushort(__float2bfloat16(v0)) |
                                      ((uint32_t)__bfloat16_as_ushort(__float2bfloat16(v1)) << 16);
                        *(uint32_t*)&ko[(size_t)row * HID + col] = pk;
                    } else {
                        float* dst = (which == 0) ? qo : vo;
                        *(float2*)&dst[(size_t)row * HID + col] = make_float2(v0, v1);
                    }
                }
            }
        }
}

__global__ void __launch_bounds__(128)
gemm_o(const __nv_bfloat16* __restrict__ Ahi, const __nv_bfloat16* __restrict__ Alo,
       const __nv_bfloat16* __restrict__ Whi, const __nv_bfloat16* __restrict__ Wlo,
       const float* __restrict__ bias, float* __restrict__ C) {
    extern __shared__ Stage stages[];
    const int n0 = blockIdx.x * BN;
    const int m0 = blockIdx.y * BM;

    float acc[2][4][4];
    mma_mainloop(Ahi, Alo, Whi, Wlo, m0, n0, stages, acc);

    const int warp = threadIdx.x >> 5, lane = threadIdx.x & 31;
    const int g = lane >> 2, t = lane & 3;
    const int wm = (warp >> 1) * 32, wn = (warp & 1) * 32;
#pragma unroll
    for (int mt = 0; mt < 2; mt++)
#pragma unroll
        for (int nt = 0; nt < 4; nt++) {
            int col = n0 + wn + nt * 8 + 2 * t;
            float b0 = bias[col], b1 = bias[col + 1];
#pragma unroll
            for (int hh = 0; hh < 2; hh++) {
                int row = m0 + wm + mt * 16 + g + hh * 8;
                if (row < N_NODES) {
                    float v0 = acc[mt][nt][2 * hh + 0] + b0;
                    float v1 = acc[mt][nt][2 * hh + 1] + b1;
                    v0 = (v0 > 0.0f) ? v0 : 0.01f * v0;
                    v1 = (v1 > 0.0f) ? v1 : 0.01f * v1;
                    *(float2*)&C[(size_t)row * HID + col] = make_float2(v0, v1);
                }
            }
        }
}

// ---------------------------------------------------------------------------
// Attention (unchanged from R5): block per node, warp per head.
// ---------------------------------------------------------------------------
__global__ __launch_bounds__(256)
void attn_kernel(const int* __restrict__ nbr, const float* __restrict__ ew,
                 __nv_bfloat16* __restrict__ agg_hi, __nv_bfloat16* __restrict__ agg_lo) {
    const int i = blockIdx.x;
    const int tid = threadIdx.x;
    const int warp = tid >> 5;
    const int lane = tid & 31;

    __shared__ __nv_bfloat16 s_k[DEG][KPAD];
    __shared__ float s_q[HID];
    __shared__ float s_w[DEG];
    __shared__ int   s_nbr[DEG];

    s_q[tid] = g_q[(size_t)i * HID + tid];

    if (warp == 0) {
        float w = ew[(size_t)i * DEG + lane];
        s_nbr[lane] = nbr[(size_t)i * DEG + lane];
        int rank = 0;
#pragma unroll
        for (int l = 0; l < DEG; l++) {
            float wl = __shfl_sync(0xffffffffu, w, l);
            rank += (wl > w) || (wl == w && l < lane);
        }
        float wm = (rank < TOPK) ? w : 0.0f;
        float s = wm;
#pragma unroll
        for (int off = 16; off; off >>= 1)
            s += __shfl_xor_sync(0xffffffffu, s, off);
        s_w[lane] = wm / (s + 1e-5f);
    }

#pragma unroll
    for (int jj = 0; jj < 4; jj++) {
        int j = warp * 4 + jj;
        int nb = __ldg(&nbr[(size_t)i * DEG + j]);
        uint4 vkb = *(const uint4*)(g_kb + (size_t)nb * HID + lane * 8);
        *(uint4*)&s_k[j][lane * 8] = vkb;
    }
    __syncthreads();

    const int hd = warp;
    const float* qh = s_q + hd * DH;
    const __nv_bfloat16* krow = &s_k[lane][hd * DH];
    float score = 0.0f;
#pragma unroll
    for (int d2 = 0; d2 < DH / 2; d2++) {
        float2 kv = __bfloat1622float2(*(const __nv_bfloat162*)(krow + d2 * 2));
        score = fmaf(kv.x, qh[d2 * 2 + 0], score);
        score = fmaf(kv.y, qh[d2 * 2 + 1], score);
    }
    float logit = score * s_w[lane] * 0.17677669529663687f;

    float m = logit;
#pragma unroll
    for (int off = 16; off; off >>= 1)
        m = fmaxf(m, __shfl_xor_sync(0xffffffffu, m, off));
    float e = __expf(logit - m);
    float se = e;
#pragma unroll
    for (int off = 16; off; off >>= 1)
        se += __shfl_xor_sync(0xffffffffu, se, off);
    float attn = e / se;

    float acc = 0.0f;
#pragma unroll
    for (int j = 0; j < DEG; j++) {
        float a = __shfl_sync(0xffffffffu, attn, j);
        acc = fmaf(a, g_v[(size_t)s_nbr[j] * HID + hd * DH + lane], acc);
    }

    __nv_bfloat16 hi = __float2bfloat16(acc);
    __nv_bfloat16 lo = __float2bfloat16(acc - __bfloat162float(hi));
    size_t o = (size_t)i * HID + hd * DH + lane;
    agg_hi[o] = hi;
    agg_lo[o] = lo;
}

// ---------------------------------------------------------------------------
// Launch
// ---------------------------------------------------------------------------
extern "C" void kernel_launch(void* const* d_in, const int* in_sizes, int n_in,
                              void* d_out, int out_size) {
    const float* h   = (const float*)d_in[0];
    const int*   nbr = (const int*)d_in[1];
    const float* ew  = (const float*)d_in[2];
    const float* W_q = (const float*)d_in[3];
    const float* b_q = (const float*)d_in[4];
    const float* W_k = (const float*)d_in[5];
    const float* b_k = (const float*)d_in[6];
    const float* W_v = (const float*)d_in[7];
    const float* b_v = (const float*)d_in[8];
    const float* W_o = (const float*)d_in[9];
    const float* b_o = (const float*)d_in[10];
    float* out = (float*)d_out;

    float *q, *v;
    __nv_bfloat16 *kb, *ah_hi, *ah_lo, *ag_hi, *ag_lo, *w_hi, *w_lo;
    cudaGetSymbolAddress((void**)&q, g_q);
    cudaGetSymbolAddress((void**)&v, g_v);
    cudaGetSymbolAddress((void**)&kb, g_kb);
    cudaGetSymbolAddress((void**)&ah_hi, g_ah_hi);
    cudaGetSymbolAddress((void**)&ah_lo, g_ah_lo);
    cudaGetSymbolAddress((void**)&ag_hi, g_ag_hi);
    cudaGetSymbolAddress((void**)&ag_lo, g_ag_lo);
    cudaGetSymbolAddress((void**)&w_hi, g_w_hi);
    cudaGetSymbolAddress((void**)&w_lo, g_w_lo);

    cudaFuncSetAttribute(gemm_qkv, cudaFuncAttributeMaxDynamicSharedMemorySize, SMEM_GEMM);
    cudaFuncSetAttribute(gemm_o,   cudaFuncAttributeMaxDynamicSharedMemorySize, SMEM_GEMM);

    const int nA8 = N_NODES * HID / 8;

    split_kernel<<<(nA8 + 255) / 256, 256>>>(h, ah_hi, ah_lo, nA8);
    split_w_kernel<<<(4 * HID * HID / 8 + 255) / 256, 256>>>(W_q, W_k, W_v, W_o, w_hi, w_lo);

    dim3 grid_qkv(12, MPAD / BM);
    gemm_qkv<<<grid_qkv, 128, SMEM_GEMM>>>(ah_hi, ah_lo, w_hi, w_lo, b_q, b_k, b_v, q, kb, v);

    attn_kernel<<<N_NODES, 256>>>(nbr, ew, ag_hi, ag_lo);

    dim3 grid_o(4, MPAD / BM);
    gemm_o<<<grid_o, 128, SMEM_GEMM>>>(ag_hi, ag_lo, w_hi + 3 * (size_t)HID * HID,
                                       w_lo + 3 * (size_t)HID * HID, b_o, out);
}

// round 7
// speedup vs baseline: 2.4420x; 1.0616x over previous
#include <cuda_runtime.h>
#include <cuda_bf16.h>
#include <cstdint>

#define N_NODES 20000
#define HID 256
#define HEADS 8
#define DH 32
#define DEG 32
#define TOPK 16

#define MPAD 20032
#define KPAD 264

// ---------------------------------------------------------------------------
// Scratch
// ---------------------------------------------------------------------------
__device__ float g_q[N_NODES * HID];
__device__ float g_v[N_NODES * HID];
__device__ __align__(16) __nv_bfloat16 g_kb[N_NODES * HID];
__device__ __align__(16) __nv_bfloat16 g_ah_hi[MPAD * HID];
__device__ __align__(16) __nv_bfloat16 g_ah_lo[MPAD * HID];
__device__ __align__(16) __nv_bfloat16 g_ag_hi[MPAD * HID];
__device__ __align__(16) __nv_bfloat16 g_ag_lo[MPAD * HID];
__device__ __align__(16) __nv_bfloat16 g_w_hi[4][HID * HID];
__device__ __align__(16) __nv_bfloat16 g_w_lo[4][HID * HID];

// ---------------------------------------------------------------------------
// Splits
// ---------------------------------------------------------------------------
__device__ __forceinline__ void split8(const float* vals, uint32_t* hw, uint32_t* lw) {
#pragma unroll
    for (int p = 0; p < 4; p++) {
        __nv_bfloat16 h0 = __float2bfloat16(vals[2 * p]);
        __nv_bfloat16 h1 = __float2bfloat16(vals[2 * p + 1]);
        __nv_bfloat16 l0 = __float2bfloat16(vals[2 * p]     - __bfloat162float(h0));
        __nv_bfloat16 l1 = __float2bfloat16(vals[2 * p + 1] - __bfloat162float(h1));
        hw[p] = (uint32_t)__bfloat16_as_ushort(h0) | ((uint32_t)__bfloat16_as_ushort(h1) << 16);
        lw[p] = (uint32_t)__bfloat16_as_ushort(l0) | ((uint32_t)__bfloat16_as_ushort(l1) << 16);
    }
}

__global__ void split_kernel(const float* __restrict__ src,
                             __nv_bfloat16* __restrict__ hi,
                             __nv_bfloat16* __restrict__ lo, int n8) {
    int g = blockIdx.x * blockDim.x + threadIdx.x;
    if (g >= n8) return;
    const float4* s = (const float4*)(src) + g * 2;
    float4 v0 = s[0], v1 = s[1];
    float vals[8] = {v0.x, v0.y, v0.z, v0.w, v1.x, v1.y, v1.z, v1.w};
    uint32_t hw[4], lw[4];
    split8(vals, hw, lw);
    *(uint4*)(hi + (size_t)g * 8) = make_uint4(hw[0], hw[1], hw[2], hw[3]);
    *(uint4*)(lo + (size_t)g * 8) = make_uint4(lw[0], lw[1], lw[2], lw[3]);
}

__global__ void split_w_kernel(const float* __restrict__ w0, const float* __restrict__ w1,
                               const float* __restrict__ w2, const float* __restrict__ w3,
                               __nv_bfloat16* __restrict__ hi, __nv_bfloat16* __restrict__ lo) {
    int g = blockIdx.x * blockDim.x + threadIdx.x;
    if (g >= 4 * (HID * HID / 8)) return;
    int wi = g >> 13, idx = g & 8191;
    const float* src = (wi == 0) ? w0 : (wi == 1) ? w1 : (wi == 2) ? w2 : w3;
    const float4* s = (const float4*)(src) + idx * 2;
    float4 v0 = s[0], v1 = s[1];
    float vals[8] = {v0.x, v0.y, v0.z, v0.w, v1.x, v1.y, v1.z, v1.w};
    uint32_t hw[4], lw[4];
    split8(vals, hw, lw);
    size_t off = (size_t)wi * HID * HID + (size_t)idx * 8;
    *(uint4*)(hi + off) = make_uint4(hw[0], hw[1], hw[2], hw[3]);
    *(uint4*)(lo + off) = make_uint4(lw[0], lw[1], lw[2], lw[3]);
}

// dummy: shifts gemm_qkv into profiled launch slot #4
__global__ void dummy_kernel() {}

// ---------------------------------------------------------------------------
// GEMM: CTA 64x64, BK=32, 3-stage cp.async, ldmatrix fragment loads.
// ---------------------------------------------------------------------------
#define BM 64
#define BN 64
#define BK 32
#define SA 40
#define STAGES 3
#define NITER (HID / BK)

struct Stage {
    __nv_bfloat16 Ah[BM][SA], Al[BM][SA], Bh[BN][SA], Bl[BN][SA];
};
#define SMEM_GEMM (STAGES * (int)sizeof(Stage))

__device__ __forceinline__ void mma16816(float* c, uint32_t a0, uint32_t a1,
                                         uint32_t a2, uint32_t a3,
                                         uint32_t b0, uint32_t b1) {
    asm volatile(
        "mma.sync.aligned.m16n8k16.row.col.f32.bf16.bf16.f32 "
        "{%0,%1,%2,%3}, {%4,%5,%6,%7}, {%8,%9}, {%0,%1,%2,%3};"
        : "+f"(c[0]), "+f"(c[1]), "+f"(c[2]), "+f"(c[3])
        : "r"(a0), "r"(a1), "r"(a2), "r"(a3), "r"(b0), "r"(b1));
}

__device__ __forceinline__ void ldmx4(uint32_t* r, const void* p) {
    uint32_t a = (uint32_t)__cvta_generic_to_shared(p);
    asm volatile("ldmatrix.sync.aligned.m8n8.x4.shared.b16 {%0,%1,%2,%3}, [%4];"
                 : "=r"(r[0]), "=r"(r[1]), "=r"(r[2]), "=r"(r[3]) : "r"(a));
}

__device__ __forceinline__ void cpa16(uint32_t dst, const void* src) {
    asm volatile("cp.async.cg.shared.global [%0], [%1], 16;" :: "r"(dst), "l"(src));
}
__device__ __forceinline__ void cpa_commit() {
    asm volatile("cp.async.commit_group;" ::: "memory");
}
__device__ __forceinline__ void cpa_wait2() {
    asm volatile("cp.async.wait_group 2;" ::: "memory");
}

__device__ __forceinline__ void prefetch_stage(
    Stage* st, const __nv_bfloat16* pA, const __nv_bfloat16* pAl,
    const __nv_bfloat16* pB, const __nv_bfloat16* pBl,
    int k0, int lrow, int lseg) {
    uint32_t a;
    a = (uint32_t)__cvta_generic_to_shared(&st->Ah[lrow][lseg]);
    cpa16(a, pA + k0);  cpa16(a + 16, pA + k0 + 8);
    a = (uint32_t)__cvta_generic_to_shared(&st->Al[lrow][lseg]);
    cpa16(a, pAl + k0); cpa16(a + 16, pAl + k0 + 8);
    a = (uint32_t)__cvta_generic_to_shared(&st->Bh[lrow][lseg]);
    cpa16(a, pB + k0);  cpa16(a + 16, pB + k0 + 8);
    a = (uint32_t)__cvta_generic_to_shared(&st->Bl[lrow][lseg]);
    cpa16(a, pBl + k0); cpa16(a + 16, pBl + k0 + 8);
}

__device__ __forceinline__ void mma_mainloop(
    const __nv_bfloat16* __restrict__ Ahi, const __nv_bfloat16* __restrict__ Alo,
    const __nv_bfloat16* __restrict__ Whi, const __nv_bfloat16* __restrict__ Wlo,
    int m0, int n0, Stage* stages, float (&acc)[2][4][4]) {
    const int tid = threadIdx.x;
    const int warp = tid >> 5, lane = tid & 31;
    const int wm = (warp >> 1) * 32, wn = (warp & 1) * 32;
    const int lrow = tid >> 1;
    const int lseg = (tid & 1) * 16;
    // ldmatrix lane-address decomposition
    const int lg = lane & 7, sel = lane >> 3;   // sel in 0..3
    const int a_row_off = (sel & 1) * 8, a_col_off = (sel >> 1) * 8;   // A matrix order
    const int b_row_off = (sel >> 1) * 8, b_col_off = (sel & 1) * 8;   // B matrix order

    const __nv_bfloat16* pA  = Ahi + (size_t)(m0 + lrow) * HID + lseg;
    const __nv_bfloat16* pAl = Alo + (size_t)(m0 + lrow) * HID + lseg;
    const __nv_bfloat16* pB  = Whi + (size_t)(n0 + lrow) * HID + lseg;
    const __nv_bfloat16* pBl = Wlo + (size_t)(n0 + lrow) * HID + lseg;

#pragma unroll
    for (int mt = 0; mt < 2; mt++)
#pragma unroll
        for (int nt = 0; nt < 4; nt++)
#pragma unroll
            for (int r = 0; r < 4; r++) acc[mt][nt][r] = 0.0f;

#pragma unroll
    for (int s = 0; s < STAGES; s++) {
        prefetch_stage(&stages[s], pA, pAl, pB, pBl, s * BK, lrow, lseg);
        cpa_commit();
    }

    for (int i = 0; i < NITER; i++) {
        cpa_wait2();
        __syncthreads();
        Stage& st = stages[i % STAGES];

#pragma unroll
        for (int ks = 0; ks < BK; ks += 16) {
            uint32_t ah[2][4], al[2][4], bq[2][4], blq[2][4];
#pragma unroll
            for (int mt = 0; mt < 2; mt++) {
                int r = wm + mt * 16 + lg + a_row_off;
                ldmx4(ah[mt], &st.Ah[r][ks + a_col_off]);
                ldmx4(al[mt], &st.Al[r][ks + a_col_off]);
            }
#pragma unroll
            for (int p = 0; p < 2; p++) {
                int n = wn + p * 16 + lg + b_row_off;
                ldmx4(bq[p],  &st.Bh[n][ks + b_col_off]);
                ldmx4(blq[p], &st.Bl[n][ks + b_col_off]);
            }
            // bq[p] = { b[2p][0], b[2p][1], b[2p+1][0], b[2p+1][1] }
#pragma unroll
            for (int mt = 0; mt < 2; mt++)
#pragma unroll
                for (int nt = 0; nt < 4; nt++) {
                    uint32_t b0 = bq[nt >> 1][(nt & 1) * 2];
                    uint32_t b1 = bq[nt >> 1][(nt & 1) * 2 + 1];
                    uint32_t c0 = blq[nt >> 1][(nt & 1) * 2];
                    uint32_t c1 = blq[nt >> 1][(nt & 1) * 2 + 1];
                    mma16816(acc[mt][nt], ah[mt][0], ah[mt][1], ah[mt][2], ah[mt][3], b0, b1);
                    mma16816(acc[mt][nt], ah[mt][0], ah[mt][1], ah[mt][2], ah[mt][3], c0, c1);
                    mma16816(acc[mt][nt], al[mt][0], al[mt][1], al[mt][2], al[mt][3], b0, b1);
                }
        }

        __syncthreads();
        if (i + STAGES < NITER)
            prefetch_stage(&stages[i % STAGES], pA, pAl, pB, pBl,
                           (i + STAGES) * BK, lrow, lseg);
        cpa_commit();
    }
}

__global__ void __launch_bounds__(128)
gemm_qkv(const __nv_bfloat16* __restrict__ Ahi, const __nv_bfloat16* __restrict__ Alo,
         const __nv_bfloat16* __restrict__ whi, const __nv_bfloat16* __restrict__ wlo,
         const float* __restrict__ bq, const float* __restrict__ bk,
         const float* __restrict__ bv,
         float* __restrict__ qo, __nv_bfloat16* __restrict__ ko, float* __restrict__ vo) {
    extern __shared__ Stage stages[];
    const int which = blockIdx.x >> 2;
    const int n0 = (blockIdx.x & 3) * BN;
    const int m0 = blockIdx.y * BM;
    const float* bias = (which == 0) ? bq : (which == 1) ? bk : bv;

    float acc[2][4][4];
    mma_mainloop(Ahi, Alo, whi + (size_t)which * HID * HID,
                 wlo + (size_t)which * HID * HID, m0, n0, stages, acc);

    const int warp = threadIdx.x >> 5, lane = threadIdx.x & 31;
    const int g = lane >> 2, t = lane & 3;
    const int wm = (warp >> 1) * 32, wn = (warp & 1) * 32;
#pragma unroll
    for (int mt = 0; mt < 2; mt++)
#pragma unroll
        for (int nt = 0; nt < 4; nt++) {
            int col = n0 + wn + nt * 8 + 2 * t;
            float b0 = bias[col], b1 = bias[col + 1];
#pragma unroll
            for (int hh = 0; hh < 2; hh++) {
                int row = m0 + wm + mt * 16 + g + hh * 8;
                if (row < N_NODES) {
                    float v0 = acc[mt][nt][2 * hh + 0] + b0;
                    float v1 = acc[mt][nt][2 * hh + 1] + b1;
                    if (which == 1) {
                        uint32_t pk = (uint32_t)__bfloat16_as_ushort(__float2bfloat16(v0)) |
                                      ((uint32_t)__bfloat16_as_ushort(__float2bfloat16(v1)) << 16);
                        *(uint32_t*)&ko[(size_t)row * HID + col] = pk;
                    } else {
                        float* dst = (which == 0) ? qo : vo;
                        *(float2*)&dst[(size_t)row * HID + col] = make_float2(v0, v1);
                    }
                }
            }
        }
}

__global__ void __launch_bounds__(128)
gemm_o(const __nv_bfloat16* __restrict__ Ahi, const __nv_bfloat16* __restrict__ Alo,
       const __nv_bfloat16* __restrict__ Whi, const __nv_bfloat16* __restrict__ Wlo,
       const float* __restrict__ bias, float* __restrict__ C) {
    extern __shared__ Stage stages[];
    const int n0 = blockIdx.x * BN;
    const int m0 = blockIdx.y * BM;

    float acc[2][4][4];
    mma_mainloop(Ahi, Alo, Whi, Wlo, m0, n0, stages, acc);

    const int warp = threadIdx.x >> 5, lane = threadIdx.x & 31;
    const int g = lane >> 2, t = lane & 3;
    const int wm = (warp >> 1) * 32, wn = (warp & 1) * 32;
#pragma unroll
    for (int mt = 0; mt < 2; mt++)
#pragma unroll
        for (int nt = 0; nt < 4; nt++) {
            int col = n0 + wn + nt * 8 + 2 * t;
            float b0 = bias[col], b1 = bias[col + 1];
#pragma unroll
            for (int hh = 0; hh < 2; hh++) {
                int row = m0 + wm + mt * 16 + g + hh * 8;
                if (row < N_NODES) {
                    float v0 = acc[mt][nt][2 * hh + 0] + b0;
                    float v1 = acc[mt][nt][2 * hh + 1] + b1;
                    v0 = (v0 > 0.0f) ? v0 : 0.01f * v0;
                    v1 = (v1 > 0.0f) ? v1 : 0.01f * v1;
                    *(float2*)&C[(size_t)row * HID + col] = make_float2(v0, v1);
                }
            }
        }
}

// ---------------------------------------------------------------------------
// Attention (unchanged)
// ---------------------------------------------------------------------------
__global__ __launch_bounds__(256)
void attn_kernel(const int* __restrict__ nbr, const float* __restrict__ ew,
                 __nv_bfloat16* __restrict__ agg_hi, __nv_bfloat16* __restrict__ agg_lo) {
    const int i = blockIdx.x;
    const int tid = threadIdx.x;
    const int warp = tid >> 5;
    const int lane = tid & 31;

    __shared__ __nv_bfloat16 s_k[DEG][KPAD];
    __shared__ float s_q[HID];
    __shared__ float s_w[DEG];
    __shared__ int   s_nbr[DEG];

    s_q[tid] = g_q[(size_t)i * HID + tid];

    if (warp == 0) {
        float w = ew[(size_t)i * DEG + lane];
        s_nbr[lane] = nbr[(size_t)i * DEG + lane];
        int rank = 0;
#pragma unroll
        for (int l = 0; l < DEG; l++) {
            float wl = __shfl_sync(0xffffffffu, w, l);
            rank += (wl > w) || (wl == w && l < lane);
        }
        float wm = (rank < TOPK) ? w : 0.0f;
        float s = wm;
#pragma unroll
        for (int off = 16; off; off >>= 1)
            s += __shfl_xor_sync(0xffffffffu, s, off);
        s_w[lane] = wm / (s + 1e-5f);
    }

#pragma unroll
    for (int jj = 0; jj < 4; jj++) {
        int j = warp * 4 + jj;
        int nb = __ldg(&nbr[(size_t)i * DEG + j]);
        uint4 vkb = *(const uint4*)(g_kb + (size_t)nb * HID + lane * 8);
        *(uint4*)&s_k[j][lane * 8] = vkb;
    }
    __syncthreads();

    const int hd = warp;
    const float* qh = s_q + hd * DH;
    const __nv_bfloat16* krow = &s_k[lane][hd * DH];
    float score = 0.0f;
#pragma unroll
    for (int d2 = 0; d2 < DH / 2; d2++) {
        float2 kv = __bfloat1622float2(*(const __nv_bfloat162*)(krow + d2 * 2));
        score = fmaf(kv.x, qh[d2 * 2 + 0], score);
        score = fmaf(kv.y, qh[d2 * 2 + 1], score);
    }
    float logit = score * s_w[lane] * 0.17677669529663687f;

    float m = logit;
#pragma unroll
    for (int off = 16; off; off >>= 1)
        m = fmaxf(m, __shfl_xor_sync(0xffffffffu, m, off));
    float e = __expf(logit - m);
    float se = e;
#pragma unroll
    for (int off = 16; off; off >>= 1)
        se += __shfl_xor_sync(0xffffffffu, se, off);
    float attn = e / se;

    float acc = 0.0f;
#pragma unroll
    for (int j = 0; j < DEG; j++) {
        float a = __shfl_sync(0xffffffffu, attn, j);
        acc = fmaf(a, g_v[(size_t)s_nbr[j] * HID + hd * DH + lane], acc);
    }

    __nv_bfloat16 hi = __float2bfloat16(acc);
    __nv_bfloat16 lo = __float2bfloat16(acc - __bfloat162float(hi));
    size_t o = (size_t)i * HID + hd * DH + lane;
    agg_hi[o] = hi;
    agg_lo[o] = lo;
}

// ---------------------------------------------------------------------------
// Launch
// ---------------------------------------------------------------------------
extern "C" void kernel_launch(void* const* d_in, const int* in_sizes, int n_in,
                              void* d_out, int out_size) {
    const float* h   = (const float*)d_in[0];
    const int*   nbr = (const int*)d_in[1];
    const float* ew  = (const float*)d_in[2];
    const float* W_q = (const float*)d_in[3];
    const float* b_q = (const float*)d_in[4];
    const float* W_k = (const float*)d_in[5];
    const float* b_k = (const float*)d_in[6];
    const float* W_v = (const float*)d_in[7];
    const float* b_v = (const float*)d_in[8];
    const float* W_o = (const float*)d_in[9];
    const float* b_o = (const float*)d_in[10];
    float* out = (float*)d_out;

    float *q, *v;
    __nv_bfloat16 *kb, *ah_hi, *ah_lo, *ag_hi, *ag_lo, *w_hi, *w_lo;
    cudaGetSymbolAddress((void**)&q, g_q);
    cudaGetSymbolAddress((void**)&v, g_v);
    cudaGetSymbolAddress((void**)&kb, g_kb);
    cudaGetSymbolAddress((void**)&ah_hi, g_ah_hi);
    cudaGetSymbolAddress((void**)&ah_lo, g_ah_lo);
    cudaGetSymbolAddress((void**)&ag_hi, g_ag_hi);
    cudaGetSymbolAddress((void**)&ag_lo, g_ag_lo);
    cudaGetSymbolAddress((void**)&w_hi, g_w_hi);
    cudaGetSymbolAddress((void**)&w_lo, g_w_lo);

    cudaFuncSetAttribute(gemm_qkv, cudaFuncAttributeMaxDynamicSharedMemorySize, SMEM_GEMM);
    cudaFuncSetAttribute(gemm_o,   cudaFuncAttributeMaxDynamicSharedMemorySize, SMEM_GEMM);

    const int nA8 = N_NODES * HID / 8;

    split_kernel<<<(nA8 + 255) / 256, 256>>>(h, ah_hi, ah_lo, nA8);          // 1
    split_w_kernel<<<(4 * HID * HID / 8 + 255) / 256, 256>>>(W_q, W_k, W_v, W_o, w_hi, w_lo); // 2
    dummy_kernel<<<1, 32>>>();                                               // 3

    dim3 grid_qkv(12, MPAD / BM);
    gemm_qkv<<<grid_qkv, 128, SMEM_GEMM>>>(ah_hi, ah_lo, w_hi, w_lo, b_q, b_k, b_v, q, kb, v); // 4 (profiled)

    attn_kernel<<<N_NODES, 256>>>(nbr, ew, ag_hi, ag_lo);                    // 5

    dim3 grid_o(4, MPAD / BM);
    gemm_o<<<grid_o, 128, SMEM_GEMM>>>(ag_hi, ag_lo, w_hi + 3 * (size_t)HID * HID,
                                       w_lo + 3 * (size_t)HID * HID, b_o, out); // 6
}

// round 8
// speedup vs baseline: 2.6354x; 1.0792x over previous
#include <cuda_runtime.h>
#include <cuda_bf16.h>
#include <cstdint>

#define N_NODES 20000
#define HID 256
#define HEADS 8
#define DH 32
#define DEG 32
#define TOPK 16

#define MPAD 20096          // multiple of 128
#define KPAD 264

// ---------------------------------------------------------------------------
// Scratch
// ---------------------------------------------------------------------------
__device__ float g_q[N_NODES * HID];
__device__ float g_v[N_NODES * HID];
__device__ __align__(16) __nv_bfloat16 g_kb[N_NODES * HID];
__device__ __align__(16) __nv_bfloat16 g_ah_hi[MPAD * HID];
__device__ __align__(16) __nv_bfloat16 g_ah_lo[MPAD * HID];
__device__ __align__(16) __nv_bfloat16 g_ag_hi[MPAD * HID];
__device__ __align__(16) __nv_bfloat16 g_ag_lo[MPAD * HID];
__device__ __align__(16) __nv_bfloat16 g_w_hi[4][HID * HID];
__device__ __align__(16) __nv_bfloat16 g_w_lo[4][HID * HID];

// ---------------------------------------------------------------------------
// Splits
// ---------------------------------------------------------------------------
__device__ __forceinline__ void split8(const float* vals, uint32_t* hw, uint32_t* lw) {
#pragma unroll
    for (int p = 0; p < 4; p++) {
        __nv_bfloat16 h0 = __float2bfloat16(vals[2 * p]);
        __nv_bfloat16 h1 = __float2bfloat16(vals[2 * p + 1]);
        __nv_bfloat16 l0 = __float2bfloat16(vals[2 * p]     - __bfloat162float(h0));
        __nv_bfloat16 l1 = __float2bfloat16(vals[2 * p + 1] - __bfloat162float(h1));
        hw[p] = (uint32_t)__bfloat16_as_ushort(h0) | ((uint32_t)__bfloat16_as_ushort(h1) << 16);
        lw[p] = (uint32_t)__bfloat16_as_ushort(l0) | ((uint32_t)__bfloat16_as_ushort(l1) << 16);
    }
}

__global__ void split_kernel(const float* __restrict__ src,
                             __nv_bfloat16* __restrict__ hi,
                             __nv_bfloat16* __restrict__ lo, int n8) {
    int g = blockIdx.x * blockDim.x + threadIdx.x;
    if (g >= n8) return;
    const float4* s = (const float4*)(src) + g * 2;
    float4 v0 = s[0], v1 = s[1];
    float vals[8] = {v0.x, v0.y, v0.z, v0.w, v1.x, v1.y, v1.z, v1.w};
    uint32_t hw[4], lw[4];
    split8(vals, hw, lw);
    *(uint4*)(hi + (size_t)g * 8) = make_uint4(hw[0], hw[1], hw[2], hw[3]);
    *(uint4*)(lo + (size_t)g * 8) = make_uint4(lw[0], lw[1], lw[2], lw[3]);
}

__global__ void split_w_kernel(const float* __restrict__ w0, const float* __restrict__ w1,
                               const float* __restrict__ w2, const float* __restrict__ w3,
                               __nv_bfloat16* __restrict__ hi, __nv_bfloat16* __restrict__ lo) {
    int g = blockIdx.x * blockDim.x + threadIdx.x;
    if (g >= 4 * (HID * HID / 8)) return;
    int wi = g >> 13, idx = g & 8191;
    const float* src = (wi == 0) ? w0 : (wi == 1) ? w1 : (wi == 2) ? w2 : w3;
    const float4* s = (const float4*)(src) + idx * 2;
    float4 v0 = s[0], v1 = s[1];
    float vals[8] = {v0.x, v0.y, v0.z, v0.w, v1.x, v1.y, v1.z, v1.w};
    uint32_t hw[4], lw[4];
    split8(vals, hw, lw);
    size_t off = (size_t)wi * HID * HID + (size_t)idx * 8;
    *(uint4*)(hi + off) = make_uint4(hw[0], hw[1], hw[2], hw[3]);
    *(uint4*)(lo + off) = make_uint4(lw[0], lw[1], lw[2], lw[3]);
}

__global__ void dummy_kernel() {}

// ---------------------------------------------------------------------------
// GEMM: CTA 128x128, BK=32, 2-stage cp.async, ldmatrix, 256 threads.
// Warp tile 64x32 (warps 2x4). 3 products: Ah*Wh + Ah*Wl + Al*Wh.
// ---------------------------------------------------------------------------
#define BM 128
#define BN 128
#define BK 32
#define SA 40
#define STAGES 2
#define NITER (HID / BK)

struct Stage {
    __nv_bfloat16 Ah[BM][SA], Al[BM][SA], Bh[BN][SA], Bl[BN][SA];
};
#define SMEM_GEMM (STAGES * (int)sizeof(Stage))

__device__ __forceinline__ void mma16816(float* c, uint32_t a0, uint32_t a1,
                                         uint32_t a2, uint32_t a3,
                                         uint32_t b0, uint32_t b1) {
    asm volatile(
        "mma.sync.aligned.m16n8k16.row.col.f32.bf16.bf16.f32 "
        "{%0,%1,%2,%3}, {%4,%5,%6,%7}, {%8,%9}, {%0,%1,%2,%3};"
        : "+f"(c[0]), "+f"(c[1]), "+f"(c[2]), "+f"(c[3])
        : "r"(a0), "r"(a1), "r"(a2), "r"(a3), "r"(b0), "r"(b1));
}

__device__ __forceinline__ void ldmx4(uint32_t* r, const void* p) {
    uint32_t a = (uint32_t)__cvta_generic_to_shared(p);
    asm volatile("ldmatrix.sync.aligned.m8n8.x4.shared.b16 {%0,%1,%2,%3}, [%4];"
                 : "=r"(r[0]), "=r"(r[1]), "=r"(r[2]), "=r"(r[3]) : "r"(a));
}

__device__ __forceinline__ void cpa16(uint32_t dst, const void* src) {
    asm volatile("cp.async.cg.shared.global [%0], [%1], 16;" :: "r"(dst), "l"(src));
}
__device__ __forceinline__ void cpa_commit() {
    asm volatile("cp.async.commit_group;" ::: "memory");
}
__device__ __forceinline__ void cpa_wait1() {
    asm volatile("cp.async.wait_group 1;" ::: "memory");
}

__device__ __forceinline__ void prefetch_stage(
    Stage* st, const __nv_bfloat16* pA, const __nv_bfloat16* pAl,
    const __nv_bfloat16* pB, const __nv_bfloat16* pBl,
    int k0, int lrow, int lseg) {
    uint32_t a;
    a = (uint32_t)__cvta_generic_to_shared(&st->Ah[lrow][lseg]);
    cpa16(a, pA + k0);  cpa16(a + 16, pA + k0 + 8);
    a = (uint32_t)__cvta_generic_to_shared(&st->Al[lrow][lseg]);
    cpa16(a, pAl + k0); cpa16(a + 16, pAl + k0 + 8);
    a = (uint32_t)__cvta_generic_to_shared(&st->Bh[lrow][lseg]);
    cpa16(a, pB + k0);  cpa16(a + 16, pB + k0 + 8);
    a = (uint32_t)__cvta_generic_to_shared(&st->Bl[lrow][lseg]);
    cpa16(a, pBl + k0); cpa16(a + 16, pBl + k0 + 8);
}

__device__ __forceinline__ void mma_mainloop(
    const __nv_bfloat16* __restrict__ Ahi, const __nv_bfloat16* __restrict__ Alo,
    const __nv_bfloat16* __restrict__ Whi, const __nv_bfloat16* __restrict__ Wlo,
    int m0, int n0, Stage* stages, float (&acc)[4][4][4]) {
    const int tid = threadIdx.x;
    const int warp = tid >> 5, lane = tid & 31;
    const int wm = (warp >> 2) * 64, wn = (warp & 3) * 32;
    const int lrow = tid >> 1;           // 0..127
    const int lseg = (tid & 1) * 16;
    const int lg = lane & 7, sel = lane >> 3;
    const int a_row_off = (sel & 1) * 8, a_col_off = (sel >> 1) * 8;
    const int b_row_off = (sel >> 1) * 8, b_col_off = (sel & 1) * 8;

    const __nv_bfloat16* pA  = Ahi + (size_t)(m0 + lrow) * HID + lseg;
    const __nv_bfloat16* pAl = Alo + (size_t)(m0 + lrow) * HID + lseg;
    const __nv_bfloat16* pB  = Whi + (size_t)(n0 + lrow) * HID + lseg;
    const __nv_bfloat16* pBl = Wlo + (size_t)(n0 + lrow) * HID + lseg;

#pragma unroll
    for (int mt = 0; mt < 4; mt++)
#pragma unroll
        for (int nt = 0; nt < 4; nt++)
#pragma unroll
            for (int r = 0; r < 4; r++) acc[mt][nt][r] = 0.0f;

#pragma unroll
    for (int s = 0; s < STAGES; s++) {
        prefetch_stage(&stages[s], pA, pAl, pB, pBl, s * BK, lrow, lseg);
        cpa_commit();
    }

    for (int i = 0; i < NITER; i++) {
        cpa_wait1();
        __syncthreads();
        Stage& st = stages[i & 1];

#pragma unroll
        for (int ks = 0; ks < BK; ks += 16) {
            uint32_t bq[2][4], blq[2][4];
#pragma unroll
            for (int p = 0; p < 2; p++) {
                int n = wn + p * 16 + lg + b_row_off;
                ldmx4(bq[p],  &st.Bh[n][ks + b_col_off]);
                ldmx4(blq[p], &st.Bl[n][ks + b_col_off]);
            }
#pragma unroll
            for (int mt = 0; mt < 4; mt++) {
                int r = wm + mt * 16 + lg + a_row_off;
                uint32_t ah[4], al[4];
                ldmx4(ah, &st.Ah[r][ks + a_col_off]);
                ldmx4(al, &st.Al[r][ks + a_col_off]);
#pragma unroll
                for (int nt = 0; nt < 4; nt++) {
                    uint32_t b0 = bq[nt >> 1][(nt & 1) * 2];
                    uint32_t b1 = bq[nt >> 1][(nt & 1) * 2 + 1];
                    uint32_t c0 = blq[nt >> 1][(nt & 1) * 2];
                    uint32_t c1 = blq[nt >> 1][(nt & 1) * 2 + 1];
                    mma16816(acc[mt][nt], ah[0], ah[1], ah[2], ah[3], b0, b1);
                    mma16816(acc[mt][nt], ah[0], ah[1], ah[2], ah[3], c0, c1);
                    mma16816(acc[mt][nt], al[0], al[1], al[2], al[3], b0, b1);
                }
            }
        }

        __syncthreads();
        if (i + STAGES < NITER)
            prefetch_stage(&stages[i & 1], pA, pAl, pB, pBl,
                           (i + STAGES) * BK, lrow, lseg);
        cpa_commit();
    }
}

__global__ void __launch_bounds__(256, 2)
gemm_qkv(const __nv_bfloat16* __restrict__ Ahi, const __nv_bfloat16* __restrict__ Alo,
         const __nv_bfloat16* __restrict__ whi, const __nv_bfloat16* __restrict__ wlo,
         const float* __restrict__ bq, const float* __restrict__ bk,
         const float* __restrict__ bv,
         float* __restrict__ qo, __nv_bfloat16* __restrict__ ko, float* __restrict__ vo) {
    extern __shared__ Stage stages[];
    const int which = blockIdx.x >> 1;          // 0..2
    const int n0 = (blockIdx.x & 1) * BN;
    const int m0 = blockIdx.y * BM;
    const float* bias = (which == 0) ? bq : (which == 1) ? bk : bv;

    float acc[4][4][4];
    mma_mainloop(Ahi, Alo, whi + (size_t)which * HID * HID,
                 wlo + (size_t)which * HID * HID, m0, n0, stages, acc);

    const int warp = threadIdx.x >> 5, lane = threadIdx.x & 31;
    const int g = lane >> 2, t = lane & 3;
    const int wm = (warp >> 2) * 64, wn = (warp & 3) * 32;
#pragma unroll
    for (int mt = 0; mt < 4; mt++) {
#pragma unroll
        for (int nt = 0; nt < 4; nt++) {
            int col = n0 + wn + nt * 8 + 2 * t;
            float b0 = bias[col], b1 = bias[col + 1];
#pragma unroll
            for (int hh = 0; hh < 2; hh++) {
                int row = m0 + wm + mt * 16 + g + hh * 8;
                if (row < N_NODES) {
                    float v0 = acc[mt][nt][2 * hh + 0] + b0;
                    float v1 = acc[mt][nt][2 * hh + 1] + b1;
                    if (which == 1) {
                        uint32_t pk = (uint32_t)__bfloat16_as_ushort(__float2bfloat16(v0)) |
                                      ((uint32_t)__bfloat16_as_ushort(__float2bfloat16(v1)) << 16);
                        *(uint32_t*)&ko[(size_t)row * HID + col] = pk;
                    } else {
                        float* dst = (which == 0) ? qo : vo;
                        *(float2*)&dst[(size_t)row * HID + col] = make_float2(v0, v1);
                    }
                }
            }
        }
    }
}

__global__ void __launch_bounds__(256, 2)
gemm_o(const __nv_bfloat16* __restrict__ Ahi, const __nv_bfloat16* __restrict__ Alo,
       const __nv_bfloat16* __restrict__ Whi, const __nv_bfloat16* __restrict__ Wlo,
       const float* __restrict__ bias, float* __restrict__ C) {
    extern __shared__ Stage stages[];
    const int n0 = blockIdx.x * BN;
    const int m0 = blockIdx.y * BM;

    float acc[4][4][4];
    mma_mainloop(Ahi, Alo, Whi, Wlo, m0, n0, stages, acc);

    const int warp = threadIdx.x >> 5, lane = threadIdx.x & 31;
    const int g = lane >> 2, t = lane & 3;
    const int wm = (warp >> 2) * 64, wn = (warp & 3) * 32;
#pragma unroll
    for (int mt = 0; mt < 4; mt++) {
#pragma unroll
        for (int nt = 0; nt < 4; nt++) {
            int col = n0 + wn + nt * 8 + 2 * t;
            float b0 = bias[col], b1 = bias[col + 1];
#pragma unroll
            for (int hh = 0; hh < 2; hh++) {
                int row = m0 + wm + mt * 16 + g + hh * 8;
                if (row < N_NODES) {
                    float v0 = acc[mt][nt][2 * hh + 0] + b0;
                    float v1 = acc[mt][nt][2 * hh + 1] + b1;
                    v0 = (v0 > 0.0f) ? v0 : 0.01f * v0;
                    v1 = (v1 > 0.0f) ? v1 : 0.01f * v1;
                    *(float2*)&C[(size_t)row * HID + col] = make_float2(v0, v1);
                }
            }
        }
    }
}

// ---------------------------------------------------------------------------
// Attention (unchanged)
// ---------------------------------------------------------------------------
__global__ __launch_bounds__(256)
void attn_kernel(const int* __restrict__ nbr, const float* __restrict__ ew,
                 __nv_bfloat16* __restrict__ agg_hi, __nv_bfloat16* __restrict__ agg_lo) {
    const int i = blockIdx.x;
    const int tid = threadIdx.x;
    const int warp = tid >> 5;
    const int lane = tid & 31;

    __shared__ __nv_bfloat16 s_k[DEG][KPAD];
    __shared__ float s_q[HID];
    __shared__ float s_w[DEG];
    __shared__ int   s_nbr[DEG];

    s_q[tid] = g_q[(size_t)i * HID + tid];

    if (warp == 0) {
        float w = ew[(size_t)i * DEG + lane];
        s_nbr[lane] = nbr[(size_t)i * DEG + lane];
        int rank = 0;
#pragma unroll
        for (int l = 0; l < DEG; l++) {
            float wl = __shfl_sync(0xffffffffu, w, l);
            rank += (wl > w) || (wl == w && l < lane);
        }
        float wm = (rank < TOPK) ? w : 0.0f;
        float s = wm;
#pragma unroll
        for (int off = 16; off; off >>= 1)
            s += __shfl_xor_sync(0xffffffffu, s, off);
        s_w[lane] = wm / (s + 1e-5f);
    }

#pragma unroll
    for (int jj = 0; jj < 4; jj++) {
        int j = warp * 4 + jj;
        int nb = __ldg(&nbr[(size_t)i * DEG + j]);
        uint4 vkb = *(const uint4*)(g_kb + (size_t)nb * HID + lane * 8);
        *(uint4*)&s_k[j][lane * 8] = vkb;
    }
    __syncthreads();

    const int hd = warp;
    const float* qh = s_q + hd * DH;
    const __nv_bfloat16* krow = &s_k[lane][hd * DH];
    float score = 0.0f;
#pragma unroll
    for (int d2 = 0; d2 < DH / 2; d2++) {
        float2 kv = __bfloat1622float2(*(const __nv_bfloat162*)(krow + d2 * 2));
        score = fmaf(kv.x, qh[d2 * 2 + 0], score);
        score = fmaf(kv.y, qh[d2 * 2 + 1], score);
    }
    float logit = score * s_w[lane] * 0.17677669529663687f;

    float m = logit;
#pragma unroll
    for (int off = 16; off; off >>= 1)
        m = fmaxf(m, __shfl_xor_sync(0xffffffffu, m, off));
    float e = __expf(logit - m);
    float se = e;
#pragma unroll
    for (int off = 16; off; off >>= 1)
        se += __shfl_xor_sync(0xffffffffu, se, off);
    float attn = e / se;

    float acc = 0.0f;
#pragma unroll
    for (int j = 0; j < DEG; j++) {
        float a = __shfl_sync(0xffffffffu, attn, j);
        acc = fmaf(a, g_v[(size_t)s_nbr[j] * HID + hd * DH + lane], acc);
    }

    __nv_bfloat16 hi = __float2bfloat16(acc);
    __nv_bfloat16 lo = __float2bfloat16(acc - __bfloat162float(hi));
    size_t o = (size_t)i * HID + hd * DH + lane;
    agg_hi[o] = hi;
    agg_lo[o] = lo;
}

// ---------------------------------------------------------------------------
// Launch
// ---------------------------------------------------------------------------
extern "C" void kernel_launch(void* const* d_in, const int* in_sizes, int n_in,
                              void* d_out, int out_size) {
    const float* h   = (const float*)d_in[0];
    const int*   nbr = (const int*)d_in[1];
    const float* ew  = (const float*)d_in[2];
    const float* W_q = (const float*)d_in[3];
    const float* b_q = (const float*)d_in[4];
    const float* W_k = (const float*)d_in[5];
    const float* b_k = (const float*)d_in[6];
    const float* W_v = (const float*)d_in[7];
    const float* b_v = (const float*)d_in[8];
    const float* W_o = (const float*)d_in[9];
    const float* b_o = (const float*)d_in[10];
    float* out = (float*)d_out;

    float *q, *v;
    __nv_bfloat16 *kb, *ah_hi, *ah_lo, *ag_hi, *ag_lo, *w_hi, *w_lo;
    cudaGetSymbolAddress((void**)&q, g_q);
    cudaGetSymbolAddress((void**)&v, g_v);
    cudaGetSymbolAddress((void**)&kb, g_kb);
    cudaGetSymbolAddress((void**)&ah_hi, g_ah_hi);
    cudaGetSymbolAddress((void**)&ah_lo, g_ah_lo);
    cudaGetSymbolAddress((void**)&ag_hi, g_ag_hi);
    cudaGetSymbolAddress((void**)&ag_lo, g_ag_lo);
    cudaGetSymbolAddress((void**)&w_hi, g_w_hi);
    cudaGetSymbolAddress((void**)&w_lo, g_w_lo);

    cudaFuncSetAttribute(gemm_qkv, cudaFuncAttributeMaxDynamicSharedMemorySize, SMEM_GEMM);
    cudaFuncSetAttribute(gemm_o,   cudaFuncAttributeMaxDynamicSharedMemorySize, SMEM_GEMM);

    const int nA8 = N_NODES * HID / 8;

    split_kernel<<<(nA8 + 255) / 256, 256>>>(h, ah_hi, ah_lo, nA8);          // 1
    split_w_kernel<<<(4 * HID * HID / 8 + 255) / 256, 256>>>(W_q, W_k, W_v, W_o, w_hi, w_lo); // 2
    dummy_kernel<<<1, 32>>>();                                               // 3

    dim3 grid_qkv(6, MPAD / BM);
    gemm_qkv<<<grid_qkv, 256, SMEM_GEMM>>>(ah_hi, ah_lo, w_hi, w_lo, b_q, b_k, b_v, q, kb, v); // 4 (profiled)

    attn_kernel<<<N_NODES, 256>>>(nbr, ew, ag_hi, ag_lo);                    // 5

    dim3 grid_o(2, MPAD / BM);
    gemm_o<<<grid_o, 256, SMEM_GEMM>>>(ag_hi, ag_lo, w_hi + 3 * (size_t)HID * HID,
                                       w_lo + 3 * (size_t)HID * HID, b_o, out); // 6
}